// round 3
// baseline (speedup 1.0000x reference)
#include <cuda_runtime.h>
#include <math.h>
#include <stdint.h>

#define HN    512
#define NST   64
#define LL    2048
#define LF    4096
#define BT    8
#define NT    256

// ---------------- scratch ----------------
__device__ float2 g_KF[HN * LF];        // kernel spectrum / 4096
__device__ float  g_UT[BT * HN * LL];   // u transposed (b,h,l)
__device__ float  g_YT[BT * HN * LL];   // y transposed (b,h,l)
__device__ float2 g_TW[2048];           // W_4096^k
__device__ float2 g_T4[4088];           // stage twiddles N=4096 (st0:512*7, st1:64*7, st2:8*7)
__device__ float2 g_T2[2044];           // stage twiddles N=2048 (st0:256*7, st1:32*7, st2:4*7)

// ---------------- helpers ----------------
__device__ __forceinline__ float2 cadd(float2 a, float2 b) { return make_float2(a.x + b.x, a.y + b.y); }
__device__ __forceinline__ float2 csub(float2 a, float2 b) { return make_float2(a.x - b.x, a.y - b.y); }
__device__ __forceinline__ float2 cmulf(float2 a, float2 b) {
    return make_float2(fmaf(a.x, b.x, -(a.y * b.y)), fmaf(a.x, b.y, a.y * b.x));
}

#define SW(u) ((u) ^ (((u) >> 3) & 15))

// f32x2 packed math
__device__ __forceinline__ unsigned long long pk2(float a, float b) {
    unsigned long long r; asm("mov.b64 %0, {%1, %2};" : "=l"(r) : "f"(a), "f"(b)); return r;
}
__device__ __forceinline__ void up2(unsigned long long v, float& a, float& b) {
    asm("mov.b64 {%0, %1}, %2;" : "=f"(a), "=f"(b) : "l"(v));
}
__device__ __forceinline__ unsigned long long f2fma(unsigned long long a, unsigned long long b, unsigned long long c) {
    unsigned long long d; asm("fma.rn.f32x2 %0, %1, %2, %3;" : "=l"(d) : "l"(a), "l"(b), "l"(c)); return d;
}
__device__ __forceinline__ unsigned long long f2add(unsigned long long a, unsigned long long b) {
    unsigned long long d; asm("add.rn.f32x2 %0, %1, %2;" : "=l"(d) : "l"(a), "l"(b)); return d;
}
__device__ __forceinline__ unsigned long long f2mul(unsigned long long a, unsigned long long b) {
    unsigned long long d; asm("mul.rn.f32x2 %0, %1, %2;" : "=l"(d) : "l"(a), "l"(b)); return d;
}
__device__ __forceinline__ float rcpa(float x) {
    float r; asm("rcp.approx.f32 %0, %1;" : "=f"(r) : "f"(x)); return r;
}
__device__ __forceinline__ float hsum(unsigned long long v) {
    float a, b; up2(v, a, b); return a + b;
}

// ---------------- twiddle tables ----------------
__global__ void k_twid() {
    int stride = gridDim.x * blockDim.x;
    int tid = blockIdx.x * blockDim.x + threadIdx.x;
    for (int k = tid; k < 2048; k += stride) {
        double s, c; sincospi(-2.0 * (double)k / 4096.0, &s, &c);
        g_TW[k] = make_float2((float)c, (float)s);
    }
    for (int e = tid; e < 4088; e += stride) {
        int p, k, ls;
        if (e < 3584)      { p = e / 7;          k = e % 7 + 1;          ls = 0; }
        else if (e < 4032) { int r = e - 3584;   p = r / 7; k = r % 7 + 1; ls = 3; }
        else               { int r = e - 4032;   p = r / 7; k = r % 7 + 1; ls = 6; }
        double ang = (double)k * (double)(p << ls);
        double s, c; sincospi(-2.0 * ang / 4096.0, &s, &c);
        g_T4[e] = make_float2((float)c, (float)s);
    }
    for (int e = tid; e < 2044; e += stride) {
        int p, k, ls;
        if (e < 1792)      { p = e / 7;          k = e % 7 + 1;          ls = 0; }
        else if (e < 2016) { int r = e - 1792;   p = r / 7; k = r % 7 + 1; ls = 3; }
        else               { int r = e - 2016;   p = r / 7; k = r % 7 + 1; ls = 6; }
        double ang = (double)k * (double)(p << ls) * 2.0;
        double s, c; sincospi(-2.0 * ang / 4096.0, &s, &c);
        g_T2[e] = make_float2((float)c, (float)s);
    }
}

// ---------------- butterflies ----------------
template <int DIR>
__device__ __forceinline__ void bfly8(const float2 v[8], float2 X[8]) {
    float2 s0 = cadd(v[0], v[4]), d0 = csub(v[0], v[4]);
    float2 s1 = cadd(v[2], v[6]), d1 = csub(v[2], v[6]);
    float2 E0 = cadd(s0, s1), E2 = csub(s0, s1);
    float2 id1 = (DIR < 0) ? make_float2(d1.y, -d1.x) : make_float2(-d1.y, d1.x);
    float2 E1 = cadd(d0, id1), E3 = csub(d0, id1);
    float2 t0 = cadd(v[1], v[5]), u0 = csub(v[1], v[5]);
    float2 t1 = cadd(v[3], v[7]), u1 = csub(v[3], v[7]);
    float2 O0 = cadd(t0, t1), O2 = csub(t0, t1);
    float2 iu1 = (DIR < 0) ? make_float2(u1.y, -u1.x) : make_float2(-u1.y, u1.x);
    float2 O1 = cadd(u0, iu1), O3 = csub(u0, iu1);
    const float c = 0.70710678118654752440f;
    float2 w1O1, w2O2, w3O3;
    if (DIR < 0) {
        w1O1 = make_float2(c * (O1.x + O1.y), c * (O1.y - O1.x));
        w2O2 = make_float2(O2.y, -O2.x);
        w3O3 = make_float2(c * (O3.y - O3.x), -c * (O3.x + O3.y));
    } else {
        w1O1 = make_float2(c * (O1.x - O1.y), c * (O1.x + O1.y));
        w2O2 = make_float2(-O2.y, O2.x);
        w3O3 = make_float2(-c * (O3.x + O3.y), c * (O3.x - O3.y));
    }
    X[0] = cadd(E0, O0);   X[4] = csub(E0, O0);
    X[1] = cadd(E1, w1O1); X[5] = csub(E1, w1O1);
    X[2] = cadd(E2, w2O2); X[6] = csub(E2, w2O2);
    X[3] = cadd(E3, w3O3); X[7] = csub(E3, w3O3);
}

template <int DIR>
__device__ __forceinline__ void bfly4(const float2 v[4], float2 X[4]) {
    float2 a = cadd(v[0], v[2]), b = csub(v[0], v[2]);
    float2 c = cadd(v[1], v[3]), d = csub(v[1], v[3]);
    float2 id = (DIR < 0) ? make_float2(d.y, -d.x) : make_float2(-d.y, d.x);
    X[0] = cadd(a, c); X[1] = cadd(b, id); X[2] = csub(a, c); X[3] = csub(b, id);
}

// ---------------- generic ping-pong radix-8 stage (caller syncs after) ----------------
template <int DIR, int LS, int N>
__device__ __forceinline__ void stage8_pp(const float2* __restrict__ xin, float2* __restrict__ xout,
                                          const float2* __restrict__ tab, int t) {
    const int B8 = N / 8;
    const int BPT = B8 / NT;
    const int S = 1 << LS;
#pragma unroll
    for (int b = 0; b < BPT; b++) {
        int i = t + b * NT;
        float2 v[8];
#pragma unroll
        for (int m = 0; m < 8; m++) v[m] = xin[SW(i + m * B8)];
        float2 X[8];
        bfly8<DIR>(v, X);
        int q = i & (S - 1), p = i >> LS;
        int wb = q + (p << (LS + 3));
        if (S == B8) {
#pragma unroll
            for (int k = 0; k < 8; k++) xout[SW(wb + k * S)] = X[k];
        } else {
            const float2* w = tab + p * 7;
            xout[SW(wb)] = X[0];
#pragma unroll
            for (int k = 1; k < 8; k++) {
                float2 wk = __ldg(&w[k - 1]);
                if (DIR > 0) wk.y = -wk.y;
                xout[SW(wb + k * S)] = cmulf(X[k], wk);
            }
        }
    }
}

// ---------------- K1: fused cauchy + kernel spectrum (one CTA per h) ----------------
__global__ void __launch_bounds__(NT, 3) k_kernel(
        const float* __restrict__ Lre, const float* __restrict__ Lim,
        const float* __restrict__ P, const float* __restrict__ B,
        const float* __restrict__ C, const float* __restrict__ logstep) {
    __shared__ ulonglong2 s_q01[32];   // {-lr pair, -li pair}
    __shared__ ulonglong2 s_q23[32];   // {w00r pair, w00i pair}
    __shared__ ulonglong2 s_q45[32];   // {w01r pair, w01i pair}
    __shared__ ulonglong2 s_q67[32];   // {w10r pair, w10i pair}
    __shared__ unsigned long long s_q8[32];  // {w11r pair}
    extern __shared__ float2 sm[];
    float2* A  = sm;          // 2048
    float2* Bf = sm + 2048;   // 2048

    int h = blockIdx.x, t = threadIdx.x;
    if (t < 32) {
        float lr[2], li[2], w00r[2], w00i[2], w01r[2], w01i[2], w10r[2], w10i[2], w11r[2];
#pragma unroll
        for (int k = 0; k < 2; k++) {
            int idx = h * NST + 2 * t + k;
            lr[k] = fminf(Lre[idx], -1e-4f);
            li[k] = Lim[idx];
            float pr = P[idx * 2], pi = P[idx * 2 + 1];
            float br = B[idx * 2], bi = B[idx * 2 + 1];
            float cr = C[idx * 2], ci = C[idx * 2 + 1];
            w00r[k] = cr * br + ci * bi;  w00i[k] = cr * bi - ci * br;
            w01r[k] = cr * pr + ci * pi;  w01i[k] = cr * pi - ci * pr;
            w10r[k] = pr * br + pi * bi;  w10i[k] = pr * bi - pi * br;
            w11r[k] = pr * pr + pi * pi;
        }
        s_q01[t] = make_ulonglong2(pk2(-lr[0], -lr[1]), pk2(-li[0], -li[1]));
        s_q23[t] = make_ulonglong2(pk2(w00r[0], w00r[1]), pk2(w00i[0], w00i[1]));
        s_q45[t] = make_ulonglong2(pk2(w01r[0], w01r[1]), pk2(w01i[0], w01i[1]));
        s_q67[t] = make_ulonglong2(pk2(w10r[0], w10r[1]), pk2(w10i[0], w10i[1]));
        s_q8[t]  = pk2(w11r[0], w11r[1]);
    }
    __syncthreads();

    float ts = 2.0f * expf(-logstep[h]);
    // ---- Cauchy phase: 8 points per thread -> A[SW(l)] ----
#pragma unroll 1
    for (int lp = 0; lp < 8; lp++) {
        int l = t + NT * lp;
        float theta = (float)l * (-2.0f * 3.14159265358979323846f / (float)LL);
        float sn, cs;
        sincosf(theta, &sn, &cs);
        float bpr = 1.0f + cs, bpi = sn;
        float amr = 1.0f - cs, ami = -sn;
        float invb = 1.0f / (bpr * bpr + bpi * bpi);
        float gr = ts * (amr * bpr + ami * bpi) * invb;
        float gi = ts * (ami * bpr - amr * bpi) * invb;
        float csr = 2.0f * bpr * invb;
        float csi = -2.0f * bpi * invb;

        unsigned long long gr2 = pk2(gr, gr), gi2 = pk2(gi, gi);
        unsigned long long S0 = 0, S1 = 0, S2 = 0, S3 = 0, S4 = 0, S5 = 0, S6 = 0;
        unsigned long long S7 = 0, S8 = 0, S9 = 0, S10 = 0, S11 = 0, S12 = 0, S13 = 0;
#pragma unroll 4
        for (int j = 0; j < 32; j++) {
            ulonglong2 q01 = s_q01[j];
            unsigned long long dr = f2add(gr2, q01.x);
            unsigned long long di = f2add(gi2, q01.y);
            unsigned long long mag = f2fma(dr, dr, f2mul(di, di));
            float m0, m1; up2(mag, m0, m1);
            unsigned long long inv = pk2(rcpa(m0), rcpa(m1));
            unsigned long long rr  = f2mul(dr, inv);
            unsigned long long nri = f2mul(di, inv);
            ulonglong2 q23 = s_q23[j];
            S0 = f2fma(q23.x, rr, S0);  S1 = f2fma(q23.y, nri, S1);
            S2 = f2fma(q23.y, rr, S2);  S3 = f2fma(q23.x, nri, S3);
            ulonglong2 q45 = s_q45[j];
            S4 = f2fma(q45.x, rr, S4);  S5 = f2fma(q45.y, nri, S5);
            S6 = f2fma(q45.y, rr, S6);  S7 = f2fma(q45.x, nri, S7);
            ulonglong2 q67 = s_q67[j];
            S8 = f2fma(q67.x, rr, S8);   S9 = f2fma(q67.y, nri, S9);
            S10 = f2fma(q67.y, rr, S10); S11 = f2fma(q67.x, nri, S11);
            unsigned long long q8 = s_q8[j];
            S12 = f2fma(q8, rr, S12);    S13 = f2fma(q8, nri, S13);
        }
        float k00r = hsum(S0) + hsum(S1),  k00i = hsum(S2) - hsum(S3);
        float k01r = hsum(S4) + hsum(S5),  k01i = hsum(S6) - hsum(S7);
        float k10r = hsum(S8) + hsum(S9),  k10i = hsum(S10) - hsum(S11);
        float k11r = hsum(S12),            k11i = -hsum(S13);

        float denr = 1.0f + k11r, deni = k11i;
        float invd = 1.0f / (denr * denr + deni * deni);
        float qr = k01r * k10r - k01i * k10i;
        float qi = k01r * k10i + k01i * k10r;
        float fr = (qr * denr + qi * deni) * invd;
        float fi = (qi * denr - qr * deni) * invd;
        float ar_ = k00r - fr, ai_ = k00i - fi;
        A[SW(l)] = make_float2(csr * ar_ - csi * ai_, csr * ai_ + csi * ar_);
    }
    __syncthreads();

    // ---- symmetrize: ats -> Bf, even KF bins to global ----
    float2* kfh = g_KF + (size_t)h * LF;
    const float s4 = 1.0f / 4096.0f;
#pragma unroll
    for (int lp = 0; lp < 8; lp++) {
        int l = t + NT * lp;
        float2 a  = A[SW(l)];
        float2 bm = A[SW((2048 - l) & 2047)];
        float2 ats = make_float2(0.5f * (a.x + bm.x), 0.5f * (a.y - bm.y));
        Bf[SW(l)] = ats;
        kfh[2 * l] = make_float2(ats.x * s4, ats.y * s4);
    }
    __syncthreads();

    // ---- ifft2048(ats): Bf->A->Bf->A, then fused radix-4 (twist) A->Bf ----
    stage8_pp<+1, 0, 2048>(Bf, A, g_T2,        t); __syncthreads();
    stage8_pp<+1, 3, 2048>(A, Bf, g_T2 + 1792, t); __syncthreads();
    stage8_pp<+1, 6, 2048>(Bf, A, g_T2 + 2016, t); __syncthreads();
#pragma unroll
    for (int b = 0; b < 2; b++) {
        int i = t + NT * b;
        float2 v[4], X[4];
#pragma unroll
        for (int m = 0; m < 4; m++) v[m] = A[SW(i + m * 512)];
        bfly4<+1>(v, X);
#pragma unroll
        for (int m = 0; m < 4; m++) {
            int l = i + m * 512;
            float kr = X[m].x * (1.0f / 2048.0f);
            float2 w = __ldg(&g_TW[l]);
            Bf[SW(l)] = make_float2(kr * w.x, kr * w.y);
        }
    }
    __syncthreads();

    // ---- fft2048(K * W^n): Bf->A->Bf->A, fused radix-4 writes odd KF bins ----
    stage8_pp<-1, 0, 2048>(Bf, A, g_T2,        t); __syncthreads();
    stage8_pp<-1, 3, 2048>(A, Bf, g_T2 + 1792, t); __syncthreads();
    stage8_pp<-1, 6, 2048>(Bf, A, g_T2 + 2016, t); __syncthreads();
#pragma unroll
    for (int b = 0; b < 2; b++) {
        int i = t + NT * b;
        float2 v[4], X[4];
#pragma unroll
        for (int m = 0; m < 4; m++) v[m] = A[SW(i + m * 512)];
        bfly4<-1>(v, X);
#pragma unroll
        for (int m = 0; m < 4; m++) {
            int l = i + m * 512;
            kfh[2 * l + 1] = make_float2(X[m].x * s4, X[m].y * s4);
        }
    }
}

// ---------------- K3: transpose u (b,l,h) -> (b,h,l) ----------------
__global__ void k_transpose_in(const float* __restrict__ u) {
    __shared__ float tile[32][33];
    int b = blockIdx.z;
    int h0 = blockIdx.x * 32, l0 = blockIdx.y * 32;
    int tx = threadIdx.x, ty = threadIdx.y;
    const float* up = u + (size_t)b * LL * HN;
#pragma unroll
    for (int j = 0; j < 32; j += 8)
        tile[ty + j][tx] = up[(size_t)(l0 + ty + j) * HN + h0 + tx];
    __syncthreads();
    float* o = g_UT + (size_t)b * HN * LL;
#pragma unroll
    for (int j = 0; j < 32; j += 8)
        o[(size_t)(h0 + ty + j) * LL + l0 + tx] = tile[tx][ty + j];
}

// ---------------- K4: fused packed conv ----------------
__global__ void __launch_bounds__(NT, 3) k_conv(const float* __restrict__ D) {
    extern __shared__ float2 sm[];
    float2* A  = sm;          // 4096
    float2* Bf = sm + 4096;   // 4096
    int blk = blockIdx.x;
    int h = blk & (HN - 1);
    int bp = blk >> 9;
    int t = threadIdx.x;
    const float* u0 = g_UT + ((size_t)(2 * bp) * HN + h) * LL;
    const float* u1 = g_UT + ((size_t)(2 * bp + 1) * HN + h) * LL;

    // F1: global -> A, fused (upper half zero)
#pragma unroll
    for (int b = 0; b < 2; b++) {
        int i = t + NT * b;
        float2 v[8], X[8];
#pragma unroll
        for (int m = 0; m < 4; m++) v[m] = make_float2(u0[i + m * 512], u1[i + m * 512]);
#pragma unroll
        for (int m = 4; m < 8; m++) v[m] = make_float2(0.0f, 0.0f);
        bfly8<-1>(v, X);
        const float2* w = g_T4 + i * 7;
        int wb = i << 3;
        A[SW(wb)] = X[0];
#pragma unroll
        for (int k = 1; k < 8; k++) A[SW(wb + k)] = cmulf(X[k], __ldg(&w[k - 1]));
    }
    __syncthreads();
    stage8_pp<-1, 3, 4096>(A, Bf, g_T4 + 3584, t); __syncthreads();
    stage8_pp<-1, 6, 4096>(Bf, A, g_T4 + 4032, t); __syncthreads();
    stage8_pp<-1, 9, 4096>(A, Bf, (const float2*)0, t); __syncthreads();

    // I1: Bf -> A, fused pointwise * KF
    const float2* kf = g_KF + (size_t)h * LF;
#pragma unroll
    for (int b = 0; b < 2; b++) {
        int i = t + NT * b;
        float2 v[8], X[8];
#pragma unroll
        for (int m = 0; m < 8; m++) v[m] = cmulf(Bf[SW(i + m * 512)], __ldg(&kf[i + m * 512]));
        bfly8<+1>(v, X);
        const float2* w = g_T4 + i * 7;
        int wb = i << 3;
        A[SW(wb)] = X[0];
#pragma unroll
        for (int k = 1; k < 8; k++) {
            float2 wk = __ldg(&w[k - 1]); wk.y = -wk.y;
            A[SW(wb + k)] = cmulf(X[k], wk);
        }
    }
    __syncthreads();
    stage8_pp<+1, 3, 4096>(A, Bf, g_T4 + 3584, t); __syncthreads();
    stage8_pp<+1, 6, 4096>(Bf, A, g_T4 + 4032, t); __syncthreads();

    // I4: A -> global, twiddle-free, keep lower 2048, add D skip
    float dv = D[h];
    float* y0 = g_YT + ((size_t)(2 * bp) * HN + h) * LL;
    float* y1 = g_YT + ((size_t)(2 * bp + 1) * HN + h) * LL;
#pragma unroll
    for (int b = 0; b < 2; b++) {
        int i = t + NT * b;
        float2 v[8], X[8];
#pragma unroll
        for (int m = 0; m < 8; m++) v[m] = A[SW(i + m * 512)];
        bfly8<+1>(v, X);
#pragma unroll
        for (int m = 0; m < 4; m++) {
            int l = i + m * 512;
            y0[l] = fmaf(dv, u0[l], X[m].x);
            y1[l] = fmaf(dv, u1[l], X[m].y);
        }
    }
}

// ---------------- K5: transpose y (b,h,l) -> out (b,l,h) ----------------
__global__ void k_transpose_out(float* __restrict__ out) {
    __shared__ float tile[32][33];
    int b = blockIdx.z;
    int l0 = blockIdx.x * 32, h0 = blockIdx.y * 32;
    int tx = threadIdx.x, ty = threadIdx.y;
    const float* yp = g_YT + (size_t)b * HN * LL;
#pragma unroll
    for (int j = 0; j < 32; j += 8)
        tile[ty + j][tx] = yp[(size_t)(h0 + ty + j) * LL + l0 + tx];
    __syncthreads();
    float* op = out + (size_t)b * LL * HN;
#pragma unroll
    for (int j = 0; j < 32; j += 8)
        op[(size_t)(l0 + ty + j) * HN + h0 + tx] = tile[tx][ty + j];
}

// ---------------- launch ----------------
extern "C" void kernel_launch(void* const* d_in, const int* in_sizes, int n_in,
                              void* d_out, int out_size) {
    const float* u   = (const float*)d_in[0];
    const float* Lre = (const float*)d_in[1];
    const float* Lim = (const float*)d_in[2];
    const float* P   = (const float*)d_in[3];
    const float* B   = (const float*)d_in[4];
    const float* C   = (const float*)d_in[5];
    const float* D   = (const float*)d_in[6];
    const float* lst = (const float*)d_in[7];

    const int smem_kf = 4096 * sizeof(float2);   // 32 KB (A+B of 2048)
    const int smem_cv = 8192 * sizeof(float2);   // 64 KB (A+B of 4096)
    cudaFuncSetAttribute(k_kernel, cudaFuncAttributeMaxDynamicSharedMemorySize, smem_kf);
    cudaFuncSetAttribute(k_conv,   cudaFuncAttributeMaxDynamicSharedMemorySize, smem_cv);

    k_twid<<<16, 256>>>();
    k_transpose_in<<<dim3(HN / 32, LL / 32, BT), dim3(32, 8)>>>(u);
    k_kernel<<<HN, NT, smem_kf>>>(Lre, Lim, P, B, C, lst);
    k_conv<<<(BT / 2) * HN, NT, smem_cv>>>(D);
    k_transpose_out<<<dim3(LL / 32, HN / 32, BT), dim3(32, 8)>>>((float*)d_out);
}

// round 4
// speedup vs baseline: 1.1170x; 1.1170x over previous
#include <cuda_runtime.h>
#include <math.h>
#include <stdint.h>

#define HN    512
#define NST   64
#define LL    2048
#define LF    4096
#define BT    8
#define NT    256

// ---------------- scratch ----------------
__device__ float2 g_AT[HN * LL];        // at_roots (h, l)
__device__ float2 g_KF[HN * LF];        // kernel spectrum / 4096
__device__ float  g_UT[BT * HN * LL];   // u transposed (b,h,l)
__device__ float  g_YT[BT * HN * LL];   // y transposed (b,h,l)
__device__ float2 g_TW[2048];           // W_4096^k

// ---------------- helpers ----------------
__device__ __forceinline__ float2 cadd(float2 a, float2 b) { return make_float2(a.x + b.x, a.y + b.y); }
__device__ __forceinline__ float2 csub(float2 a, float2 b) { return make_float2(a.x - b.x, a.y - b.y); }
__device__ __forceinline__ float2 cmulf(float2 a, float2 b) {
    return make_float2(fmaf(a.x, b.x, -(a.y * b.y)), fmaf(a.x, b.y, a.y * b.x));
}
#define SW(u) ((u) ^ (((u) >> 3) & 15))

// f32x2 packed math (cauchy)
__device__ __forceinline__ unsigned long long pk2(float a, float b) {
    unsigned long long r; asm("mov.b64 %0, {%1, %2};" : "=l"(r) : "f"(a), "f"(b)); return r;
}
__device__ __forceinline__ void up2(unsigned long long v, float& a, float& b) {
    asm("mov.b64 {%0, %1}, %2;" : "=f"(a), "=f"(b) : "l"(v));
}
__device__ __forceinline__ unsigned long long f2fma(unsigned long long a, unsigned long long b, unsigned long long c) {
    unsigned long long d; asm("fma.rn.f32x2 %0, %1, %2, %3;" : "=l"(d) : "l"(a), "l"(b), "l"(c)); return d;
}
__device__ __forceinline__ unsigned long long f2add(unsigned long long a, unsigned long long b) {
    unsigned long long d; asm("add.rn.f32x2 %0, %1, %2;" : "=l"(d) : "l"(a), "l"(b)); return d;
}
__device__ __forceinline__ unsigned long long f2mul(unsigned long long a, unsigned long long b) {
    unsigned long long d; asm("mul.rn.f32x2 %0, %1, %2;" : "=l"(d) : "l"(a), "l"(b)); return d;
}
__device__ __forceinline__ float rcpa(float x) {
    float r; asm("rcp.approx.f32 %0, %1;" : "=f"(r) : "f"(x)); return r;
}
__device__ __forceinline__ float hsum(unsigned long long v) {
    float a, b; up2(v, a, b); return a + b;
}

// ---------------- twiddle table ----------------
__global__ void k_twiddle() {
    int k = blockIdx.x * blockDim.x + threadIdx.x;
    if (k < 2048) {
        double s, c;
        sincospi(-2.0 * (double)k / 4096.0, &s, &c);
        g_TW[k] = make_float2((float)c, (float)s);
    }
}

// ================= proven round-2 path: cauchy + kernel spectrum =================
template <int DIR>
__device__ __forceinline__ void bfly8(const float2 v[8], float2 X[8]) {
    float2 s0 = cadd(v[0], v[4]), d0 = csub(v[0], v[4]);
    float2 s1 = cadd(v[2], v[6]), d1 = csub(v[2], v[6]);
    float2 E0 = cadd(s0, s1), E2 = csub(s0, s1);
    float2 id1 = (DIR < 0) ? make_float2(d1.y, -d1.x) : make_float2(-d1.y, d1.x);
    float2 E1 = cadd(d0, id1), E3 = csub(d0, id1);
    float2 t0 = cadd(v[1], v[5]), u0 = csub(v[1], v[5]);
    float2 t1 = cadd(v[3], v[7]), u1 = csub(v[3], v[7]);
    float2 O0 = cadd(t0, t1), O2 = csub(t0, t1);
    float2 iu1 = (DIR < 0) ? make_float2(u1.y, -u1.x) : make_float2(-u1.y, u1.x);
    float2 O1 = cadd(u0, iu1), O3 = csub(u0, iu1);
    const float c = 0.70710678118654752440f;
    float2 w1O1, w2O2, w3O3;
    if (DIR < 0) {
        w1O1 = make_float2(c * (O1.x + O1.y), c * (O1.y - O1.x));
        w2O2 = make_float2(O2.y, -O2.x);
        w3O3 = make_float2(c * (O3.y - O3.x), -c * (O3.x + O3.y));
    } else {
        w1O1 = make_float2(c * (O1.x - O1.y), c * (O1.x + O1.y));
        w2O2 = make_float2(-O2.y, O2.x);
        w3O3 = make_float2(-c * (O3.x + O3.y), c * (O3.x - O3.y));
    }
    X[0] = cadd(E0, O0);   X[4] = csub(E0, O0);
    X[1] = cadd(E1, w1O1); X[5] = csub(E1, w1O1);
    X[2] = cadd(E2, w2O2); X[6] = csub(E2, w2O2);
    X[3] = cadd(E3, w3O3); X[7] = csub(E3, w3O3);
}

// in-place swizzled Stockham (N=2048: 3 radix-8 + final radix-4), round-2 proven
template <int N, int DIR>
__device__ __forceinline__ void fft_ip(float2* x, const float2* __restrict__ tw, int t) {
    const int MULT = LF / N;
    const int B8 = N / 8;
    const int BPT = B8 / NT;
    int s = 1, ls = 0;
#pragma unroll
    for (int st = 0; st < 3; st++) {
        float2 v[BPT ? BPT : 1][8];
#pragma unroll
        for (int b = 0; b < BPT; b++) {
            int i = t + b * NT;
#pragma unroll
            for (int m = 0; m < 8; m++) v[b][m] = x[SW(i + m * B8)];
        }
        __syncthreads();
#pragma unroll
        for (int b = 0; b < BPT; b++) {
            int i = t + b * NT;
            int q = i & (s - 1), p = i >> ls;
            float2 X[8];
            bfly8<DIR>(v[b], X);
            int pt = (p << ls) * MULT;
            float2 w1 = tw[pt], w2 = tw[2 * pt], w3 = tw[3 * pt];
            if (DIR > 0) { w1.y = -w1.y; w2.y = -w2.y; w3.y = -w3.y; }
            float2 w4 = cmulf(w2, w2), w5 = cmulf(w2, w3);
            float2 w6 = cmulf(w3, w3), w7 = cmulf(w3, w4);
            int wb = q + (p << (ls + 3));
            x[SW(wb)]         = X[0];
            x[SW(wb + s)]     = cmulf(X[1], w1);
            x[SW(wb + 2 * s)] = cmulf(X[2], w2);
            x[SW(wb + 3 * s)] = cmulf(X[3], w3);
            x[SW(wb + 4 * s)] = cmulf(X[4], w4);
            x[SW(wb + 5 * s)] = cmulf(X[5], w5);
            x[SW(wb + 6 * s)] = cmulf(X[6], w6);
            x[SW(wb + 7 * s)] = cmulf(X[7], w7);
        }
        __syncthreads();
        s <<= 3; ls += 3;
    }
    // final radix-4, s=512, twiddle-free
    float2 v[2][4];
#pragma unroll
    for (int b = 0; b < 2; b++) {
        int i = t + b * NT;
#pragma unroll
        for (int m = 0; m < 4; m++) v[b][m] = x[SW(i + m * 512)];
    }
    __syncthreads();
#pragma unroll
    for (int b = 0; b < 2; b++) {
        int i = t + b * NT;
        float2 a = cadd(v[b][0], v[b][2]), bb = csub(v[b][0], v[b][2]);
        float2 c = cadd(v[b][1], v[b][3]), d = csub(v[b][1], v[b][3]);
        float2 id = (DIR < 0) ? make_float2(d.y, -d.x) : make_float2(-d.y, d.x);
        x[SW(i)]        = cadd(a, c);
        x[SW(i + 512)]  = cadd(bb, id);
        x[SW(i + 1024)] = csub(a, c);
        x[SW(i + 1536)] = csub(bb, id);
    }
    __syncthreads();
}

// ---------------- K1: Cauchy / at_roots ----------------
__global__ void __launch_bounds__(NT) k_cauchy(
        const float* __restrict__ Lre, const float* __restrict__ Lim,
        const float* __restrict__ P, const float* __restrict__ B,
        const float* __restrict__ C, const float* __restrict__ logstep) {
    __shared__ float4 s_q0[32];
    __shared__ float4 s_q1[32];
    __shared__ float4 s_q2[32];
    __shared__ float4 s_q3[32];
    __shared__ float2 s_q4[32];
    int h = blockIdx.y;
    int t = threadIdx.x;
    if (t < 32) {
        float lr[2], li[2], w00r[2], w00i[2], w01r[2], w01i[2], w10r[2], w10i[2], w11r[2];
#pragma unroll
        for (int k = 0; k < 2; k++) {
            int idx = h * NST + 2 * t + k;
            lr[k] = fminf(Lre[idx], -1e-4f);
            li[k] = Lim[idx];
            float pr = P[idx * 2], pi = P[idx * 2 + 1];
            float br = B[idx * 2], bi = B[idx * 2 + 1];
            float cr = C[idx * 2], ci = C[idx * 2 + 1];
            w00r[k] = cr * br + ci * bi;  w00i[k] = cr * bi - ci * br;
            w01r[k] = cr * pr + ci * pi;  w01i[k] = cr * pi - ci * pr;
            w10r[k] = pr * br + pi * bi;  w10i[k] = pr * bi - pi * br;
            w11r[k] = pr * pr + pi * pi;
        }
        s_q0[t] = make_float4(-lr[0], -lr[1], -li[0], -li[1]);
        s_q1[t] = make_float4(w00r[0], w00r[1], w00i[0], w00i[1]);
        s_q2[t] = make_float4(w01r[0], w01r[1], w01i[0], w01i[1]);
        s_q3[t] = make_float4(w10r[0], w10r[1], w10i[0], w10i[1]);
        s_q4[t] = make_float2(w11r[0], w11r[1]);
    }
    __syncthreads();

    int l = blockIdx.x * NT + t;
    float ts = 2.0f * expf(-logstep[h]);
    float theta = (float)l * (-2.0f * 3.14159265358979323846f / (float)LL);
    float sn, cs;
    sincosf(theta, &sn, &cs);
    float bpr = 1.0f + cs, bpi = sn;
    float amr = 1.0f - cs, ami = -sn;
    float invb = 1.0f / (bpr * bpr + bpi * bpi);
    float gr = ts * (amr * bpr + ami * bpi) * invb;
    float gi = ts * (ami * bpr - amr * bpi) * invb;
    float csr = 2.0f * bpr * invb;
    float csi = -2.0f * bpi * invb;

    unsigned long long gr2 = pk2(gr, gr), gi2 = pk2(gi, gi);
    unsigned long long S0 = 0, S1 = 0, S2 = 0, S3 = 0, S4 = 0, S5 = 0, S6 = 0;
    unsigned long long S7 = 0, S8 = 0, S9 = 0, S10 = 0, S11 = 0, S12 = 0, S13 = 0;
#pragma unroll 8
    for (int j = 0; j < 32; j++) {
        float4 q0 = s_q0[j];
        unsigned long long dr = f2add(gr2, pk2(q0.x, q0.y));
        unsigned long long di = f2add(gi2, pk2(q0.z, q0.w));
        unsigned long long mag = f2fma(dr, dr, f2mul(di, di));
        float m0, m1; up2(mag, m0, m1);
        unsigned long long inv = pk2(rcpa(m0), rcpa(m1));
        unsigned long long rr  = f2mul(dr, inv);
        unsigned long long nri = f2mul(di, inv);
        float4 q1 = s_q1[j];
        unsigned long long wr = pk2(q1.x, q1.y), wi = pk2(q1.z, q1.w);
        S0 = f2fma(wr, rr, S0);  S1 = f2fma(wi, nri, S1);
        S2 = f2fma(wi, rr, S2);  S3 = f2fma(wr, nri, S3);
        float4 q2 = s_q2[j];
        wr = pk2(q2.x, q2.y); wi = pk2(q2.z, q2.w);
        S4 = f2fma(wr, rr, S4);  S5 = f2fma(wi, nri, S5);
        S6 = f2fma(wi, rr, S6);  S7 = f2fma(wr, nri, S7);
        float4 q3 = s_q3[j];
        wr = pk2(q3.x, q3.y); wi = pk2(q3.z, q3.w);
        S8 = f2fma(wr, rr, S8);   S9 = f2fma(wi, nri, S9);
        S10 = f2fma(wi, rr, S10); S11 = f2fma(wr, nri, S11);
        float2 q4 = s_q4[j];
        wr = pk2(q4.x, q4.y);
        S12 = f2fma(wr, rr, S12); S13 = f2fma(wr, nri, S13);
    }
    float k00r = hsum(S0) + hsum(S1),  k00i = hsum(S2) - hsum(S3);
    float k01r = hsum(S4) + hsum(S5),  k01i = hsum(S6) - hsum(S7);
    float k10r = hsum(S8) + hsum(S9),  k10i = hsum(S10) - hsum(S11);
    float k11r = hsum(S12),            k11i = -hsum(S13);

    float denr = 1.0f + k11r, deni = k11i;
    float invd = 1.0f / (denr * denr + deni * deni);
    float qr = k01r * k10r - k01i * k10i;
    float qi = k01r * k10i + k01i * k10r;
    float fr = (qr * denr + qi * deni) * invd;
    float fi = (qi * denr - qr * deni) * invd;
    float ar_ = k00r - fr, ai_ = k00i - fi;
    g_AT[h * LL + l] = make_float2(csr * ar_ - csi * ai_, csr * ai_ + csi * ar_);
}

// ---------------- K2: kernel spectrum via even/odd split (round-2 proven) ----------------
__global__ void __launch_bounds__(NT) k_kernelfft() {
    extern __shared__ float2 sm[];
    float2* buf = sm;          // 2048
    float2* stw = sm + 2048;   // 2048
    int h = blockIdx.x, t = threadIdx.x;
    for (int i = t; i < 2048; i += NT) stw[i] = g_TW[i];
    for (int i = t; i < 2048; i += NT) buf[SW(i)] = g_AT[h * LL + i];
    __syncthreads();
    float2 a[8], bm[8];
#pragma unroll
    for (int j = 0; j < 8; j++) {
        int l = t + j * NT;
        a[j] = buf[SW(l)];
        bm[j] = buf[SW((2048 - l) & 2047)];
    }
    __syncthreads();
    float2* kfh = g_KF + (size_t)h * LF;
    const float s4 = 1.0f / 4096.0f;
#pragma unroll
    for (int j = 0; j < 8; j++) {
        int l = t + j * NT;
        float2 ats = make_float2(0.5f * (a[j].x + bm[j].x), 0.5f * (a[j].y - bm[j].y));
        buf[SW(l)] = ats;
        kfh[2 * l] = make_float2(ats.x * s4, ats.y * s4);
    }
    __syncthreads();
    fft_ip<2048, +1>(buf, stw, t);
#pragma unroll
    for (int j = 0; j < 8; j++) {
        int l = t + j * NT;
        float kr = buf[SW(l)].x * (1.0f / 2048.0f);
        float2 w = stw[l];
        buf[SW(l)] = make_float2(kr * w.x, kr * w.y);
    }
    __syncthreads();
    fft_ip<2048, -1>(buf, stw, t);
#pragma unroll
    for (int j = 0; j < 8; j++) {
        int l = t + j * NT;
        float2 v = buf[SW(l)];
        kfh[2 * l + 1] = make_float2(v.x * s4, v.y * s4);
    }
}

// ================= new conv: register radix-16, 2 exchanges per 4096-FFT =================

// 16-point FFT, natural order in/out; DIR<0 forward (W = e^{-2pi i/16})
template <int DIR>
__device__ __forceinline__ void fft16(float2 v[16]) {
    const float C1 = 0.9238795325112867f;
    const float S1 = 0.3826834323650898f;
    const float R2 = 0.7071067811865476f;
    const float sg = (DIR < 0) ? -1.0f : 1.0f;
    float2 u[16];
#pragma unroll
    for (int j = 0; j < 4; j++) {
        float2 a = v[j], b = v[j + 4], c = v[j + 8], d = v[j + 12];
        float2 A0 = cadd(a, c), A1 = csub(a, c);
        float2 B0 = cadd(b, d), B1 = csub(b, d);
        float2 iB1 = (DIR < 0) ? make_float2(B1.y, -B1.x) : make_float2(-B1.y, B1.x);
        u[j]      = cadd(A0, B0);
        u[4 + j]  = cadd(A1, iB1);
        u[8 + j]  = csub(A0, B0);
        u[12 + j] = csub(A1, iB1);
    }
    u[5]  = cmulf(u[5],  make_float2(C1,  sg * S1));   // W^1
    u[6]  = cmulf(u[6],  make_float2(R2,  sg * R2));   // W^2
    u[7]  = cmulf(u[7],  make_float2(S1,  sg * C1));   // W^3
    u[9]  = cmulf(u[9],  make_float2(R2,  sg * R2));   // W^2
    u[10] = (DIR < 0) ? make_float2(u[10].y, -u[10].x) : make_float2(-u[10].y, u[10].x); // W^4
    u[11] = cmulf(u[11], make_float2(-R2, sg * R2));   // W^6
    u[13] = cmulf(u[13], make_float2(S1,  sg * C1));   // W^3
    u[14] = cmulf(u[14], make_float2(-R2, sg * R2));   // W^6
    u[15] = cmulf(u[15], make_float2(-C1, -sg * S1));  // W^9
#pragma unroll
    for (int k = 0; k < 4; k++) {
        float2 a = u[k * 4 + 0], b = u[k * 4 + 1], c = u[k * 4 + 2], d = u[k * 4 + 3];
        float2 A0 = cadd(a, c), A1 = csub(a, c);
        float2 B0 = cadd(b, d), B1 = csub(b, d);
        float2 iB1 = (DIR < 0) ? make_float2(B1.y, -B1.x) : make_float2(-B1.y, B1.x);
        v[k]      = cadd(A0, B0);
        v[k + 4]  = cadd(A1, iB1);
        v[k + 8]  = csub(A0, B0);
        v[k + 12] = csub(A1, iB1);
    }
}

// multiply v[1..15] by W^(base*k) chain, base twiddle wt (conj if CONJ)
template <int CONJ>
__device__ __forceinline__ void twchain(float2 v[16], float2 wt) {
    if (CONJ) wt.y = -wt.y;
    float2 w = wt;
#pragma unroll
    for (int k = 1; k < 16; k++) {
        v[k] = cmulf(v[k], w);
        if (k < 15) w = cmulf(w, wt);
    }
}

#define PAD_ROW 257

__global__ void __launch_bounds__(NT) k_conv(const float* __restrict__ D) {
    extern __shared__ float2 S[];       // S0[4112] | S1[4112]
    float2* S0 = S;
    float2* S1 = S + 4112;
    int blk = blockIdx.x;
    int h = blk & (HN - 1);
    int bp = blk >> 9;
    int t = threadIdx.x;
    const float* u0 = g_UT + ((size_t)(2 * bp) * HN + h) * LL;
    const float* u1 = g_UT + ((size_t)(2 * bp + 1) * HN + h) * LL;

    float2 v[16];
    // ---- forward: load (zero-padded), phase 1 ----
#pragma unroll
    for (int a = 0; a < 8; a++) v[a] = make_float2(u0[a * 256 + t], u1[a * 256 + t]);
#pragma unroll
    for (int a = 8; a < 16; a++) v[a] = make_float2(0.0f, 0.0f);
    fft16<-1>(v);
    twchain<0>(v, g_TW[t]);                              // W_4096^{t*k1}
    {   // exchange 1: S0[k1*257 + t]
#pragma unroll
        for (int k1 = 0; k1 < 16; k1++) S0[k1 * PAD_ROW + t] = v[k1];
    }
    __syncthreads();
    int c = t & 15, k1 = t >> 4;                          // phase-2 logical (k1, c)
#pragma unroll
    for (int b = 0; b < 16; b++) v[b] = S0[k1 * PAD_ROW + b * 16 + c];
    fft16<-1>(v);
    twchain<0>(v, g_TW[c << 4]);                          // W_256^{c*k2}
    {   // exchange 2: S1[c*257 + 16*k1 + k2]
#pragma unroll
        for (int k2 = 0; k2 < 16; k2++) S1[c * PAD_ROW + (k1 << 4) + k2] = v[k2];
    }
    __syncthreads();
#pragma unroll
    for (int cc = 0; cc < 16; cc++) v[cc] = S1[cc * PAD_ROW + t];  // (k1n,k2n) = t
    fft16<-1>(v);
    // thread t = 16*k1n + k2n holds X[k1n + 16*k2n + 256*k3] = X[tinv + 256*k3]
    int tinv = ((t & 15) << 4) | (t >> 4);

    // ---- pointwise * KF/4096 ----
    const float2* kf = g_KF + (size_t)h * LF;
#pragma unroll
    for (int k3 = 0; k3 < 16; k3++) v[k3] = cmulf(v[k3], __ldg(&kf[tinv + (k3 << 8)]));

    // ---- inverse (sequence index tau = tinv), conj twiddles ----
    fft16<+1>(v);
    twchain<1>(v, g_TW[tinv]);                            // W_4096^{-tinv*j1}
    {   // exchange 1 (nibble-swapped offset): S0[j1*257 + (tinv>>4) + 16*(tinv&15)]
        int off = (tinv >> 4) + ((tinv & 15) << 4);
#pragma unroll
        for (int j1 = 0; j1 < 16; j1++) S0[j1 * PAD_ROW + off] = v[j1];
    }
    __syncthreads();
    int ct2 = t >> 4, j1b = t & 15;                       // phase-2 logical (j1b, ct2)
#pragma unroll
    for (int bt = 0; bt < 16; bt++) v[bt] = S0[j1b * PAD_ROW + bt + (ct2 << 4)];
    fft16<+1>(v);
    twchain<1>(v, g_TW[ct2 << 4]);                        // W_256^{-ct2*j2}
    {   // exchange 2: S1[ct2*257 + 16*j2 + j1b]
#pragma unroll
        for (int j2 = 0; j2 < 16; j2++) S1[ct2 * PAD_ROW + (j2 << 4) + j1b] = v[j2];
    }
    __syncthreads();
#pragma unroll
    for (int ct3 = 0; ct3 < 16; ct3++) v[ct3] = S1[ct3 * PAD_ROW + t];  // (j1,j2)=t
    fft16<+1>(v);
    // thread t holds y[t + 256*j3]; keep j3<8, add D*u skip
    float dv = D[h];
    float* y0 = g_YT + ((size_t)(2 * bp) * HN + h) * LL;
    float* y1 = g_YT + ((size_t)(2 * bp + 1) * HN + h) * LL;
#pragma unroll
    for (int j3 = 0; j3 < 8; j3++) {
        int n = t + (j3 << 8);
        y0[n] = fmaf(dv, u0[n], v[j3].x);
        y1[n] = fmaf(dv, u1[n], v[j3].y);
    }
}

// ---------------- transposes ----------------
__global__ void k_transpose_in(const float* __restrict__ u) {
    __shared__ float tile[32][33];
    int b = blockIdx.z;
    int h0 = blockIdx.x * 32, l0 = blockIdx.y * 32;
    int tx = threadIdx.x, ty = threadIdx.y;
    const float* up = u + (size_t)b * LL * HN;
#pragma unroll
    for (int j = 0; j < 32; j += 8)
        tile[ty + j][tx] = up[(size_t)(l0 + ty + j) * HN + h0 + tx];
    __syncthreads();
    float* o = g_UT + (size_t)b * HN * LL;
#pragma unroll
    for (int j = 0; j < 32; j += 8)
        o[(size_t)(h0 + ty + j) * LL + l0 + tx] = tile[tx][ty + j];
}

__global__ void k_transpose_out(float* __restrict__ out) {
    __shared__ float tile[32][33];
    int b = blockIdx.z;
    int l0 = blockIdx.x * 32, h0 = blockIdx.y * 32;
    int tx = threadIdx.x, ty = threadIdx.y;
    const float* yp = g_YT + (size_t)b * HN * LL;
#pragma unroll
    for (int j = 0; j < 32; j += 8)
        tile[ty + j][tx] = yp[(size_t)(h0 + ty + j) * LL + l0 + tx];
    __syncthreads();
    float* op = out + (size_t)b * LL * HN;
#pragma unroll
    for (int j = 0; j < 32; j += 8)
        op[(size_t)(l0 + ty + j) * HN + h0 + tx] = tile[tx][ty + j];
}

// ---------------- launch ----------------
extern "C" void kernel_launch(void* const* d_in, const int* in_sizes, int n_in,
                              void* d_out, int out_size) {
    const float* u   = (const float*)d_in[0];
    const float* Lre = (const float*)d_in[1];
    const float* Lim = (const float*)d_in[2];
    const float* P   = (const float*)d_in[3];
    const float* B   = (const float*)d_in[4];
    const float* C   = (const float*)d_in[5];
    const float* D   = (const float*)d_in[6];
    const float* lst = (const float*)d_in[7];

    const int smem_kf = 4096 * sizeof(float2);          // 32 KB
    const int smem_cv = 2 * 4112 * sizeof(float2);      // 65792 B
    cudaFuncSetAttribute(k_kernelfft, cudaFuncAttributeMaxDynamicSharedMemorySize, smem_kf);
    cudaFuncSetAttribute(k_conv,      cudaFuncAttributeMaxDynamicSharedMemorySize, smem_cv);

    k_twiddle<<<2, 1024>>>();
    k_cauchy<<<dim3(LL / NT, HN), NT>>>(Lre, Lim, P, B, C, lst);
    k_transpose_in<<<dim3(HN / 32, LL / 32, BT), dim3(32, 8)>>>(u);
    k_kernelfft<<<HN, NT, smem_kf>>>();
    k_conv<<<(BT / 2) * HN, NT, smem_cv>>>(D);
    k_transpose_out<<<dim3(LL / 32, HN / 32, BT), dim3(32, 8)>>>((float*)d_out);
}

// round 5
// speedup vs baseline: 1.1762x; 1.0530x over previous
#include <cuda_runtime.h>
#include <math.h>
#include <stdint.h>

#define HN    512
#define NST   64
#define LL    2048
#define LF    4096
#define BT    8
#define NT    256
#define NK    128

// ---------------- scratch ----------------
__device__ float2 g_AT[HN * LL];        // at_roots (h, l)
__device__ float2 g_KF[HN * LF];        // kernel spectrum / 4096
__device__ float  g_UT[BT * HN * LL];   // u transposed (b,h,l)
__device__ float  g_YT[BT * HN * LL];   // y transposed (b,h,l)
__device__ float2 g_TW[2048];           // W_4096^k

// ---------------- helpers ----------------
__device__ __forceinline__ float2 cadd(float2 a, float2 b) { return make_float2(a.x + b.x, a.y + b.y); }
__device__ __forceinline__ float2 csub(float2 a, float2 b) { return make_float2(a.x - b.x, a.y - b.y); }
__device__ __forceinline__ float2 cmulf(float2 a, float2 b) {
    return make_float2(fmaf(a.x, b.x, -(a.y * b.y)), fmaf(a.x, b.y, a.y * b.x));
}

// f32x2 packed math (cauchy)
__device__ __forceinline__ unsigned long long pk2(float a, float b) {
    unsigned long long r; asm("mov.b64 %0, {%1, %2};" : "=l"(r) : "f"(a), "f"(b)); return r;
}
__device__ __forceinline__ void up2(unsigned long long v, float& a, float& b) {
    asm("mov.b64 {%0, %1}, %2;" : "=f"(a), "=f"(b) : "l"(v));
}
__device__ __forceinline__ unsigned long long f2fma(unsigned long long a, unsigned long long b, unsigned long long c) {
    unsigned long long d; asm("fma.rn.f32x2 %0, %1, %2, %3;" : "=l"(d) : "l"(a), "l"(b), "l"(c)); return d;
}
__device__ __forceinline__ unsigned long long f2add(unsigned long long a, unsigned long long b) {
    unsigned long long d; asm("add.rn.f32x2 %0, %1, %2;" : "=l"(d) : "l"(a), "l"(b)); return d;
}
__device__ __forceinline__ unsigned long long f2mul(unsigned long long a, unsigned long long b) {
    unsigned long long d; asm("mul.rn.f32x2 %0, %1, %2;" : "=l"(d) : "l"(a), "l"(b)); return d;
}
__device__ __forceinline__ float rcpa(float x) {
    float r; asm("rcp.approx.f32 %0, %1;" : "=f"(r) : "f"(x)); return r;
}
__device__ __forceinline__ float hsum(unsigned long long v) {
    float a, b; up2(v, a, b); return a + b;
}

// ---------------- twiddle table ----------------
__global__ void k_twiddle() {
    int k = blockIdx.x * blockDim.x + threadIdx.x;
    if (k < 2048) {
        double s, c;
        sincospi(-2.0 * (double)k / 4096.0, &s, &c);
        g_TW[k] = make_float2((float)c, (float)s);
    }
}

// ---------------- register butterflies ----------------
// 8-point DFT natural order; DIR<0 forward
template <int DIR>
__device__ __forceinline__ void bfly8(const float2 v[8], float2 X[8]) {
    float2 s0 = cadd(v[0], v[4]), d0 = csub(v[0], v[4]);
    float2 s1 = cadd(v[2], v[6]), d1 = csub(v[2], v[6]);
    float2 E0 = cadd(s0, s1), E2 = csub(s0, s1);
    float2 id1 = (DIR < 0) ? make_float2(d1.y, -d1.x) : make_float2(-d1.y, d1.x);
    float2 E1 = cadd(d0, id1), E3 = csub(d0, id1);
    float2 t0 = cadd(v[1], v[5]), u0 = csub(v[1], v[5]);
    float2 t1 = cadd(v[3], v[7]), u1 = csub(v[3], v[7]);
    float2 O0 = cadd(t0, t1), O2 = csub(t0, t1);
    float2 iu1 = (DIR < 0) ? make_float2(u1.y, -u1.x) : make_float2(-u1.y, u1.x);
    float2 O1 = cadd(u0, iu1), O3 = csub(u0, iu1);
    const float c = 0.70710678118654752440f;
    float2 w1O1, w2O2, w3O3;
    if (DIR < 0) {
        w1O1 = make_float2(c * (O1.x + O1.y), c * (O1.y - O1.x));
        w2O2 = make_float2(O2.y, -O2.x);
        w3O3 = make_float2(c * (O3.y - O3.x), -c * (O3.x + O3.y));
    } else {
        w1O1 = make_float2(c * (O1.x - O1.y), c * (O1.x + O1.y));
        w2O2 = make_float2(-O2.y, O2.x);
        w3O3 = make_float2(-c * (O3.x + O3.y), c * (O3.x - O3.y));
    }
    X[0] = cadd(E0, O0);   X[4] = csub(E0, O0);
    X[1] = cadd(E1, w1O1); X[5] = csub(E1, w1O1);
    X[2] = cadd(E2, w2O2); X[6] = csub(E2, w2O2);
    X[3] = cadd(E3, w3O3); X[7] = csub(E3, w3O3);
}

// 16-point FFT, natural order in/out; DIR<0 forward
template <int DIR>
__device__ __forceinline__ void fft16(float2 v[16]) {
    const float C1 = 0.9238795325112867f;
    const float S1 = 0.3826834323650898f;
    const float R2 = 0.7071067811865476f;
    const float sg = (DIR < 0) ? -1.0f : 1.0f;
    float2 u[16];
#pragma unroll
    for (int j = 0; j < 4; j++) {
        float2 a = v[j], b = v[j + 4], c = v[j + 8], d = v[j + 12];
        float2 A0 = cadd(a, c), A1 = csub(a, c);
        float2 B0 = cadd(b, d), B1 = csub(b, d);
        float2 iB1 = (DIR < 0) ? make_float2(B1.y, -B1.x) : make_float2(-B1.y, B1.x);
        u[j]      = cadd(A0, B0);
        u[4 + j]  = cadd(A1, iB1);
        u[8 + j]  = csub(A0, B0);
        u[12 + j] = csub(A1, iB1);
    }
    u[5]  = cmulf(u[5],  make_float2(C1,  sg * S1));
    u[6]  = cmulf(u[6],  make_float2(R2,  sg * R2));
    u[7]  = cmulf(u[7],  make_float2(S1,  sg * C1));
    u[9]  = cmulf(u[9],  make_float2(R2,  sg * R2));
    u[10] = (DIR < 0) ? make_float2(u[10].y, -u[10].x) : make_float2(-u[10].y, u[10].x);
    u[11] = cmulf(u[11], make_float2(-R2, sg * R2));
    u[13] = cmulf(u[13], make_float2(S1,  sg * C1));
    u[14] = cmulf(u[14], make_float2(-R2, sg * R2));
    u[15] = cmulf(u[15], make_float2(-C1, -sg * S1));
#pragma unroll
    for (int k = 0; k < 4; k++) {
        float2 a = u[k * 4 + 0], b = u[k * 4 + 1], c = u[k * 4 + 2], d = u[k * 4 + 3];
        float2 A0 = cadd(a, c), A1 = csub(a, c);
        float2 B0 = cadd(b, d), B1 = csub(b, d);
        float2 iB1 = (DIR < 0) ? make_float2(B1.y, -B1.x) : make_float2(-B1.y, B1.x);
        v[k]      = cadd(A0, B0);
        v[k + 4]  = cadd(A1, iB1);
        v[k + 8]  = csub(A0, B0);
        v[k + 12] = csub(A1, iB1);
    }
}

// multiply v[1..15] by W^(base*k) chain; conj base if CONJ
template <int CONJ>
__device__ __forceinline__ void twchain(float2 v[16], float2 wt) {
    if (CONJ) wt.y = -wt.y;
    float2 w = wt;
#pragma unroll
    for (int k = 1; k < 16; k++) {
        v[k] = cmulf(v[k], w);
        if (k < 15) w = cmulf(w, wt);
    }
}

// ---------------- K1: Cauchy / at_roots (round-2 proven) ----------------
__global__ void __launch_bounds__(NT) k_cauchy(
        const float* __restrict__ Lre, const float* __restrict__ Lim,
        const float* __restrict__ P, const float* __restrict__ B,
        const float* __restrict__ C, const float* __restrict__ logstep) {
    __shared__ float4 s_q0[32];
    __shared__ float4 s_q1[32];
    __shared__ float4 s_q2[32];
    __shared__ float4 s_q3[32];
    __shared__ float2 s_q4[32];
    int h = blockIdx.y;
    int t = threadIdx.x;
    if (t < 32) {
        float lr[2], li[2], w00r[2], w00i[2], w01r[2], w01i[2], w10r[2], w10i[2], w11r[2];
#pragma unroll
        for (int k = 0; k < 2; k++) {
            int idx = h * NST + 2 * t + k;
            lr[k] = fminf(Lre[idx], -1e-4f);
            li[k] = Lim[idx];
            float pr = P[idx * 2], pi = P[idx * 2 + 1];
            float br = B[idx * 2], bi = B[idx * 2 + 1];
            float cr = C[idx * 2], ci = C[idx * 2 + 1];
            w00r[k] = cr * br + ci * bi;  w00i[k] = cr * bi - ci * br;
            w01r[k] = cr * pr + ci * pi;  w01i[k] = cr * pi - ci * pr;
            w10r[k] = pr * br + pi * bi;  w10i[k] = pr * bi - pi * br;
            w11r[k] = pr * pr + pi * pi;
        }
        s_q0[t] = make_float4(-lr[0], -lr[1], -li[0], -li[1]);
        s_q1[t] = make_float4(w00r[0], w00r[1], w00i[0], w00i[1]);
        s_q2[t] = make_float4(w01r[0], w01r[1], w01i[0], w01i[1]);
        s_q3[t] = make_float4(w10r[0], w10r[1], w10i[0], w10i[1]);
        s_q4[t] = make_float2(w11r[0], w11r[1]);
    }
    __syncthreads();

    int l = blockIdx.x * NT + t;
    float ts = 2.0f * expf(-logstep[h]);
    float theta = (float)l * (-2.0f * 3.14159265358979323846f / (float)LL);
    float sn, cs;
    sincosf(theta, &sn, &cs);
    float bpr = 1.0f + cs, bpi = sn;
    float amr = 1.0f - cs, ami = -sn;
    float invb = 1.0f / (bpr * bpr + bpi * bpi);
    float gr = ts * (amr * bpr + ami * bpi) * invb;
    float gi = ts * (ami * bpr - amr * bpi) * invb;
    float csr = 2.0f * bpr * invb;
    float csi = -2.0f * bpi * invb;

    unsigned long long gr2 = pk2(gr, gr), gi2 = pk2(gi, gi);
    unsigned long long S0 = 0, S1 = 0, S2 = 0, S3 = 0, S4 = 0, S5 = 0, S6 = 0;
    unsigned long long S7 = 0, S8 = 0, S9 = 0, S10 = 0, S11 = 0, S12 = 0, S13 = 0;
#pragma unroll 8
    for (int j = 0; j < 32; j++) {
        float4 q0 = s_q0[j];
        unsigned long long dr = f2add(gr2, pk2(q0.x, q0.y));
        unsigned long long di = f2add(gi2, pk2(q0.z, q0.w));
        unsigned long long mag = f2fma(dr, dr, f2mul(di, di));
        float m0, m1; up2(mag, m0, m1);
        unsigned long long inv = pk2(rcpa(m0), rcpa(m1));
        unsigned long long rr  = f2mul(dr, inv);
        unsigned long long nri = f2mul(di, inv);
        float4 q1 = s_q1[j];
        unsigned long long wr = pk2(q1.x, q1.y), wi = pk2(q1.z, q1.w);
        S0 = f2fma(wr, rr, S0);  S1 = f2fma(wi, nri, S1);
        S2 = f2fma(wi, rr, S2);  S3 = f2fma(wr, nri, S3);
        float4 q2 = s_q2[j];
        wr = pk2(q2.x, q2.y); wi = pk2(q2.z, q2.w);
        S4 = f2fma(wr, rr, S4);  S5 = f2fma(wi, nri, S5);
        S6 = f2fma(wi, rr, S6);  S7 = f2fma(wr, nri, S7);
        float4 q3 = s_q3[j];
        wr = pk2(q3.x, q3.y); wi = pk2(q3.z, q3.w);
        S8 = f2fma(wr, rr, S8);   S9 = f2fma(wi, nri, S9);
        S10 = f2fma(wi, rr, S10); S11 = f2fma(wr, nri, S11);
        float2 q4 = s_q4[j];
        wr = pk2(q4.x, q4.y);
        S12 = f2fma(wr, rr, S12); S13 = f2fma(wr, nri, S13);
    }
    float k00r = hsum(S0) + hsum(S1),  k00i = hsum(S2) - hsum(S3);
    float k01r = hsum(S4) + hsum(S5),  k01i = hsum(S6) - hsum(S7);
    float k10r = hsum(S8) + hsum(S9),  k10i = hsum(S10) - hsum(S11);
    float k11r = hsum(S12),            k11i = -hsum(S13);

    float denr = 1.0f + k11r, deni = k11i;
    float invd = 1.0f / (denr * denr + deni * deni);
    float qr = k01r * k10r - k01i * k10i;
    float qi = k01r * k10i + k01i * k10r;
    float fr = (qr * denr + qi * deni) * invd;
    float fi = (qi * denr - qr * deni) * invd;
    float ar_ = k00r - fr, ai_ = k00i - fi;
    g_AT[h * LL + l] = make_float2(csr * ar_ - csi * ai_, csr * ai_ + csi * ar_);
}

// ---------------- K2: kernel spectrum, register radix-16 (2048 = 16*16*8) ----------------
// 128 threads, one h per CTA. ifft2048(ats) -> twist W_4096^n -> fft2048 -> odd bins.
#define P1 136   // pitch, 16 rows (k1-major) x 128 — conflict-free (8*k1 mod 16 splits half-warp)
#define P2 258   // pitch, 8 rows (t2-major) x 256 — (2*t2 + k1) mod 16 distinct per half-warp

__global__ void __launch_bounds__(NK) k_kernelfft() {
    __shared__ float2 S0[16 * P1];   // 2176
    __shared__ float2 S1[16 * P1];   // 2176 (reused as pitched / flat)
    int h = blockIdx.x, t = threadIdx.x;
    const float2* ath = g_AT + (size_t)h * LL;
    float2* kfh = g_KF + (size_t)h * LF;
    const float s2 = 1.0f / 2048.0f, s4 = 1.0f / 4096.0f;
    float2 v[16];

    // ---- inverse phase 1: load ats (symmetrize), even KF bins out ----
#pragma unroll
    for (int a = 0; a < 16; a++) {
        int n = a * NK + t;
        float2 x = ath[n];
        float2 m = ath[(2048 - n) & 2047];
        float2 ats = make_float2(0.5f * (x.x + m.x), 0.5f * (x.y - m.y));
        v[a] = ats;
        kfh[2 * n] = make_float2(ats.x * s4, ats.y * s4);
    }
    fft16<+1>(v);
    twchain<1>(v, g_TW[2 * t]);                    // conj W_2048^{t*k1}
#pragma unroll
    for (int k1 = 0; k1 < 16; k1++) S0[k1 * P1 + t] = v[k1];
    __syncthreads();

    int k1t = t >> 3, t2 = t & 7;
#pragma unroll
    for (int a2 = 0; a2 < 16; a2++) v[a2] = S0[k1t * P1 + a2 * 8 + t2];
    fft16<+1>(v);
    twchain<1>(v, g_TW[32 * t2]);                  // conj W_128^{t2*k2}
#pragma unroll
    for (int k2 = 0; k2 < 16; k2++) S1[t2 * P2 + k2 * 16 + k1t] = v[k2];
    __syncthreads();

    // ---- inverse phase 3 (fft8) + twist -> S0 flat (time order) ----
#pragma unroll
    for (int e = 0; e < 2; e++) {
        int pr = t + NK * e;
        int k1 = pr & 15, k2 = pr >> 4;
        float2 w[8], X[8];
#pragma unroll
        for (int s = 0; s < 8; s++) w[s] = S1[s * P2 + k2 * 16 + k1];
        bfly8<+1>(w, X);
#pragma unroll
        for (int k3 = 0; k3 < 8; k3++) {
            int n = k1 + 16 * k2 + 256 * k3;
            float kr = X[k3].x * s2;               // K[n], real
            float2 tw = g_TW[n];                   // W_4096^n
            S0[n] = make_float2(kr * tw.x, kr * tw.y);
        }
    }
    __syncthreads();

    // ---- forward phase 1 ----
#pragma unroll
    for (int a = 0; a < 16; a++) v[a] = S0[a * NK + t];
    fft16<-1>(v);
    twchain<0>(v, g_TW[2 * t]);
#pragma unroll
    for (int k1 = 0; k1 < 16; k1++) S1[k1 * P1 + t] = v[k1];
    __syncthreads();

#pragma unroll
    for (int a2 = 0; a2 < 16; a2++) v[a2] = S1[k1t * P1 + a2 * 8 + t2];
    fft16<-1>(v);
    twchain<0>(v, g_TW[32 * t2]);
#pragma unroll
    for (int k2 = 0; k2 < 16; k2++) S0[t2 * P2 + k2 * 16 + k1t] = v[k2];
    __syncthreads();

    // ---- forward phase 3: odd KF bins ----
#pragma unroll
    for (int e = 0; e < 2; e++) {
        int pr = t + NK * e;
        int k1 = pr & 15, k2 = pr >> 4;
        float2 w[8], X[8];
#pragma unroll
        for (int s = 0; s < 8; s++) w[s] = S0[s * P2 + k2 * 16 + k1];
        bfly8<-1>(w, X);
#pragma unroll
        for (int k3 = 0; k3 < 8; k3++) {
            int j = k1 + 16 * k2 + 256 * k3;
            kfh[2 * j + 1] = make_float2(X[k3].x * s4, X[k3].y * s4);
        }
    }
}

// ================= conv: register radix-16 (round-4 proven) =================
#define PAD_ROW 257

__global__ void __launch_bounds__(NT) k_conv(const float* __restrict__ D) {
    extern __shared__ float2 S[];       // S0[4112] | S1[4112]
    float2* S0 = S;
    float2* S1 = S + 4112;
    int blk = blockIdx.x;
    int h = blk & (HN - 1);
    int bp = blk >> 9;
    int t = threadIdx.x;
    const float* u0 = g_UT + ((size_t)(2 * bp) * HN + h) * LL;
    const float* u1 = g_UT + ((size_t)(2 * bp + 1) * HN + h) * LL;

    float2 v[16];
#pragma unroll
    for (int a = 0; a < 8; a++) v[a] = make_float2(u0[a * 256 + t], u1[a * 256 + t]);
#pragma unroll
    for (int a = 8; a < 16; a++) v[a] = make_float2(0.0f, 0.0f);
    fft16<-1>(v);
    twchain<0>(v, g_TW[t]);
    {
#pragma unroll
        for (int k1 = 0; k1 < 16; k1++) S0[k1 * PAD_ROW + t] = v[k1];
    }
    __syncthreads();
    int c = t & 15, k1 = t >> 4;
#pragma unroll
    for (int b = 0; b < 16; b++) v[b] = S0[k1 * PAD_ROW + b * 16 + c];
    fft16<-1>(v);
    twchain<0>(v, g_TW[c << 4]);
    {
#pragma unroll
        for (int k2 = 0; k2 < 16; k2++) S1[c * PAD_ROW + (k1 << 4) + k2] = v[k2];
    }
    __syncthreads();
#pragma unroll
    for (int cc = 0; cc < 16; cc++) v[cc] = S1[cc * PAD_ROW + t];
    fft16<-1>(v);
    int tinv = ((t & 15) << 4) | (t >> 4);

    const float2* kf = g_KF + (size_t)h * LF;
#pragma unroll
    for (int k3 = 0; k3 < 16; k3++) v[k3] = cmulf(v[k3], __ldg(&kf[tinv + (k3 << 8)]));

    fft16<+1>(v);
    twchain<1>(v, g_TW[tinv]);
    {
        int off = (tinv >> 4) + ((tinv & 15) << 4);
#pragma unroll
        for (int j1 = 0; j1 < 16; j1++) S0[j1 * PAD_ROW + off] = v[j1];
    }
    __syncthreads();
    int ct2 = t >> 4, j1b = t & 15;
#pragma unroll
    for (int bt = 0; bt < 16; bt++) v[bt] = S0[j1b * PAD_ROW + bt + (ct2 << 4)];
    fft16<+1>(v);
    twchain<1>(v, g_TW[ct2 << 4]);
    {
#pragma unroll
        for (int j2 = 0; j2 < 16; j2++) S1[ct2 * PAD_ROW + (j2 << 4) + j1b] = v[j2];
    }
    __syncthreads();
#pragma unroll
    for (int ct3 = 0; ct3 < 16; ct3++) v[ct3] = S1[ct3 * PAD_ROW + t];
    fft16<+1>(v);
    float dv = D[h];
    float* y0 = g_YT + ((size_t)(2 * bp) * HN + h) * LL;
    float* y1 = g_YT + ((size_t)(2 * bp + 1) * HN + h) * LL;
#pragma unroll
    for (int j3 = 0; j3 < 8; j3++) {
        int n = t + (j3 << 8);
        y0[n] = fmaf(dv, u0[n], v[j3].x);
        y1[n] = fmaf(dv, u1[n], v[j3].y);
    }
}

// ---------------- transposes ----------------
__global__ void k_transpose_in(const float* __restrict__ u) {
    __shared__ float tile[32][33];
    int b = blockIdx.z;
    int h0 = blockIdx.x * 32, l0 = blockIdx.y * 32;
    int tx = threadIdx.x, ty = threadIdx.y;
    const float* up = u + (size_t)b * LL * HN;
#pragma unroll
    for (int j = 0; j < 32; j += 8)
        tile[ty + j][tx] = up[(size_t)(l0 + ty + j) * HN + h0 + tx];
    __syncthreads();
    float* o = g_UT + (size_t)b * HN * LL;
#pragma unroll
    for (int j = 0; j < 32; j += 8)
        o[(size_t)(h0 + ty + j) * LL + l0 + tx] = tile[tx][ty + j];
}

__global__ void k_transpose_out(float* __restrict__ out) {
    __shared__ float tile[32][33];
    int b = blockIdx.z;
    int l0 = blockIdx.x * 32, h0 = blockIdx.y * 32;
    int tx = threadIdx.x, ty = threadIdx.y;
    const float* yp = g_YT + (size_t)b * HN * LL;
#pragma unroll
    for (int j = 0; j < 32; j += 8)
        tile[ty + j][tx] = yp[(size_t)(h0 + ty + j) * LL + l0 + tx];
    __syncthreads();
    float* op = out + (size_t)b * LL * HN;
#pragma unroll
    for (int j = 0; j < 32; j += 8)
        op[(size_t)(l0 + ty + j) * HN + h0 + tx] = tile[tx][ty + j];
}

// ---------------- launch ----------------
extern "C" void kernel_launch(void* const* d_in, const int* in_sizes, int n_in,
                              void* d_out, int out_size) {
    const float* u   = (const float*)d_in[0];
    const float* Lre = (const float*)d_in[1];
    const float* Lim = (const float*)d_in[2];
    const float* P   = (const float*)d_in[3];
    const float* B   = (const float*)d_in[4];
    const float* C   = (const float*)d_in[5];
    const float* D   = (const float*)d_in[6];
    const float* lst = (const float*)d_in[7];

    const int smem_cv = 2 * 4112 * sizeof(float2);      // 65792 B
    cudaFuncSetAttribute(k_conv, cudaFuncAttributeMaxDynamicSharedMemorySize, smem_cv);

    k_twiddle<<<2, 1024>>>();
    k_cauchy<<<dim3(LL / NT, HN), NT>>>(Lre, Lim, P, B, C, lst);
    k_transpose_in<<<dim3(HN / 32, LL / 32, BT), dim3(32, 8)>>>(u);
    k_kernelfft<<<HN, NK>>>();
    k_conv<<<(BT / 2) * HN, NT, smem_cv>>>(D);
    k_transpose_out<<<dim3(LL / 32, HN / 32, BT), dim3(32, 8)>>>((float*)d_out);
}

// round 6
// speedup vs baseline: 1.4334x; 1.2187x over previous
#include <cuda_runtime.h>
#include <math.h>
#include <stdint.h>

#define HN    512
#define NST   64
#define LL    2048
#define LF    4096
#define BT    8
#define NT    256
#define NK    128

// ---------------- scratch ----------------
__device__ float2 g_AT[HN * LL];        // at_roots (h, l)
__device__ float2 g_KF[HN * LF];        // kernel spectrum / 4096
__device__ float  g_UT[BT * HN * LL];   // u transposed (b,h,l)
__device__ float  g_YT[BT * HN * LL];   // y transposed (b,h,l)
__device__ float2 g_TW[2048];           // W_4096^k

// ---------------- helpers ----------------
__device__ __forceinline__ float2 cadd(float2 a, float2 b) { return make_float2(a.x + b.x, a.y + b.y); }
__device__ __forceinline__ float2 csub(float2 a, float2 b) { return make_float2(a.x - b.x, a.y - b.y); }
__device__ __forceinline__ float2 cmulf(float2 a, float2 b) {
    return make_float2(fmaf(a.x, b.x, -(a.y * b.y)), fmaf(a.x, b.y, a.y * b.x));
}

// f32x2 packed math (cauchy)
__device__ __forceinline__ unsigned long long pk2(float a, float b) {
    unsigned long long r; asm("mov.b64 %0, {%1, %2};" : "=l"(r) : "f"(a), "f"(b)); return r;
}
__device__ __forceinline__ void up2(unsigned long long v, float& a, float& b) {
    asm("mov.b64 {%0, %1}, %2;" : "=f"(a), "=f"(b) : "l"(v));
}
__device__ __forceinline__ unsigned long long f2fma(unsigned long long a, unsigned long long b, unsigned long long c) {
    unsigned long long d; asm("fma.rn.f32x2 %0, %1, %2, %3;" : "=l"(d) : "l"(a), "l"(b), "l"(c)); return d;
}
__device__ __forceinline__ unsigned long long f2add(unsigned long long a, unsigned long long b) {
    unsigned long long d; asm("add.rn.f32x2 %0, %1, %2;" : "=l"(d) : "l"(a), "l"(b)); return d;
}
__device__ __forceinline__ unsigned long long f2mul(unsigned long long a, unsigned long long b) {
    unsigned long long d; asm("mul.rn.f32x2 %0, %1, %2;" : "=l"(d) : "l"(a), "l"(b)); return d;
}
__device__ __forceinline__ float rcpa(float x) {
    float r; asm("rcp.approx.f32 %0, %1;" : "=f"(r) : "f"(x)); return r;
}
__device__ __forceinline__ float hsum(unsigned long long v) {
    float a, b; up2(v, a, b); return a + b;
}

// ---------------- register butterflies ----------------
template <int DIR>
__device__ __forceinline__ void bfly8(const float2 v[8], float2 X[8]) {
    float2 s0 = cadd(v[0], v[4]), d0 = csub(v[0], v[4]);
    float2 s1 = cadd(v[2], v[6]), d1 = csub(v[2], v[6]);
    float2 E0 = cadd(s0, s1), E2 = csub(s0, s1);
    float2 id1 = (DIR < 0) ? make_float2(d1.y, -d1.x) : make_float2(-d1.y, d1.x);
    float2 E1 = cadd(d0, id1), E3 = csub(d0, id1);
    float2 t0 = cadd(v[1], v[5]), u0 = csub(v[1], v[5]);
    float2 t1 = cadd(v[3], v[7]), u1 = csub(v[3], v[7]);
    float2 O0 = cadd(t0, t1), O2 = csub(t0, t1);
    float2 iu1 = (DIR < 0) ? make_float2(u1.y, -u1.x) : make_float2(-u1.y, u1.x);
    float2 O1 = cadd(u0, iu1), O3 = csub(u0, iu1);
    const float c = 0.70710678118654752440f;
    float2 w1O1, w2O2, w3O3;
    if (DIR < 0) {
        w1O1 = make_float2(c * (O1.x + O1.y), c * (O1.y - O1.x));
        w2O2 = make_float2(O2.y, -O2.x);
        w3O3 = make_float2(c * (O3.y - O3.x), -c * (O3.x + O3.y));
    } else {
        w1O1 = make_float2(c * (O1.x - O1.y), c * (O1.x + O1.y));
        w2O2 = make_float2(-O2.y, O2.x);
        w3O3 = make_float2(-c * (O3.x + O3.y), c * (O3.x - O3.y));
    }
    X[0] = cadd(E0, O0);   X[4] = csub(E0, O0);
    X[1] = cadd(E1, w1O1); X[5] = csub(E1, w1O1);
    X[2] = cadd(E2, w2O2); X[6] = csub(E2, w2O2);
    X[3] = cadd(E3, w3O3); X[7] = csub(E3, w3O3);
}

template <int DIR>
__device__ __forceinline__ void fft16(float2 v[16]) {
    const float C1 = 0.9238795325112867f;
    const float S1 = 0.3826834323650898f;
    const float R2 = 0.7071067811865476f;
    const float sg = (DIR < 0) ? -1.0f : 1.0f;
    float2 u[16];
#pragma unroll
    for (int j = 0; j < 4; j++) {
        float2 a = v[j], b = v[j + 4], c = v[j + 8], d = v[j + 12];
        float2 A0 = cadd(a, c), A1 = csub(a, c);
        float2 B0 = cadd(b, d), B1 = csub(b, d);
        float2 iB1 = (DIR < 0) ? make_float2(B1.y, -B1.x) : make_float2(-B1.y, B1.x);
        u[j]      = cadd(A0, B0);
        u[4 + j]  = cadd(A1, iB1);
        u[8 + j]  = csub(A0, B0);
        u[12 + j] = csub(A1, iB1);
    }
    u[5]  = cmulf(u[5],  make_float2(C1,  sg * S1));
    u[6]  = cmulf(u[6],  make_float2(R2,  sg * R2));
    u[7]  = cmulf(u[7],  make_float2(S1,  sg * C1));
    u[9]  = cmulf(u[9],  make_float2(R2,  sg * R2));
    u[10] = (DIR < 0) ? make_float2(u[10].y, -u[10].x) : make_float2(-u[10].y, u[10].x);
    u[11] = cmulf(u[11], make_float2(-R2, sg * R2));
    u[13] = cmulf(u[13], make_float2(S1,  sg * C1));
    u[14] = cmulf(u[14], make_float2(-R2, sg * R2));
    u[15] = cmulf(u[15], make_float2(-C1, -sg * S1));
#pragma unroll
    for (int k = 0; k < 4; k++) {
        float2 a = u[k * 4 + 0], b = u[k * 4 + 1], c = u[k * 4 + 2], d = u[k * 4 + 3];
        float2 A0 = cadd(a, c), A1 = csub(a, c);
        float2 B0 = cadd(b, d), B1 = csub(b, d);
        float2 iB1 = (DIR < 0) ? make_float2(B1.y, -B1.x) : make_float2(-B1.y, B1.x);
        v[k]      = cadd(A0, B0);
        v[k + 4]  = cadd(A1, iB1);
        v[k + 8]  = csub(A0, B0);
        v[k + 12] = csub(A1, iB1);
    }
}

template <int CONJ>
__device__ __forceinline__ void twchain(float2 v[16], float2 wt) {
    if (CONJ) wt.y = -wt.y;
    float2 w = wt;
#pragma unroll
    for (int k = 1; k < 16; k++) {
        v[k] = cmulf(v[k], w);
        if (k < 15) w = cmulf(w, wt);
    }
}

// ================= K_pre: fused twiddle + transpose_in + cauchy =================

__device__ __forceinline__ void cauchy_body(
        int i, int t, char* smraw,
        const float* __restrict__ Lre, const float* __restrict__ Lim,
        const float* __restrict__ P, const float* __restrict__ B,
        const float* __restrict__ C, const float* __restrict__ logstep) {
    ulonglong2* s_q01 = (ulonglong2*)smraw;          // 32
    ulonglong2* s_q23 = s_q01 + 32;
    ulonglong2* s_q45 = s_q23 + 32;
    ulonglong2* s_q67 = s_q45 + 32;
    unsigned long long* s_q8 = (unsigned long long*)(s_q67 + 32);
    int h = i >> 3;
    int bx = i & 7;
    if (t < 32) {
        float lr[2], li[2], w00r[2], w00i[2], w01r[2], w01i[2], w10r[2], w10i[2], w11r[2];
#pragma unroll
        for (int k = 0; k < 2; k++) {
            int idx = h * NST + 2 * t + k;
            lr[k] = fminf(Lre[idx], -1e-4f);
            li[k] = Lim[idx];
            float pr = P[idx * 2], pi = P[idx * 2 + 1];
            float br = B[idx * 2], bi = B[idx * 2 + 1];
            float cr = C[idx * 2], ci = C[idx * 2 + 1];
            w00r[k] = cr * br + ci * bi;  w00i[k] = cr * bi - ci * br;
            w01r[k] = cr * pr + ci * pi;  w01i[k] = cr * pi - ci * pr;
            w10r[k] = pr * br + pi * bi;  w10i[k] = pr * bi - pi * br;
            w11r[k] = pr * pr + pi * pi;
        }
        s_q01[t] = make_ulonglong2(pk2(-lr[0], -lr[1]), pk2(-li[0], -li[1]));
        s_q23[t] = make_ulonglong2(pk2(w00r[0], w00r[1]), pk2(w00i[0], w00i[1]));
        s_q45[t] = make_ulonglong2(pk2(w01r[0], w01r[1]), pk2(w01i[0], w01i[1]));
        s_q67[t] = make_ulonglong2(pk2(w10r[0], w10r[1]), pk2(w10i[0], w10i[1]));
        s_q8[t]  = pk2(w11r[0], w11r[1]);
    }
    __syncthreads();

    int l = bx * NT + t;
    float ts = 2.0f * expf(-logstep[h]);
    float theta = (float)l * (-2.0f * 3.14159265358979323846f / (float)LL);
    float sn, cs;
    sincosf(theta, &sn, &cs);
    float bpr = 1.0f + cs, bpi = sn;
    float amr = 1.0f - cs, ami = -sn;
    float invb = 1.0f / (bpr * bpr + bpi * bpi);
    float gr = ts * (amr * bpr + ami * bpi) * invb;
    float gi = ts * (ami * bpr - amr * bpi) * invb;
    float csr = 2.0f * bpr * invb;
    float csi = -2.0f * bpi * invb;

    unsigned long long gr2 = pk2(gr, gr), gi2 = pk2(gi, gi);
    unsigned long long S0 = 0, S1 = 0, S2 = 0, S3 = 0, S4 = 0, S5 = 0, S6 = 0;
    unsigned long long S7 = 0, S8 = 0, S9 = 0, S10 = 0, S11 = 0, S12 = 0, S13 = 0;
#pragma unroll 8
    for (int j = 0; j < 32; j++) {
        ulonglong2 q01 = s_q01[j];
        unsigned long long dr = f2add(gr2, q01.x);
        unsigned long long di = f2add(gi2, q01.y);
        unsigned long long mag = f2fma(dr, dr, f2mul(di, di));
        float m0, m1; up2(mag, m0, m1);
        unsigned long long inv = pk2(rcpa(m0), rcpa(m1));
        unsigned long long rr  = f2mul(dr, inv);
        unsigned long long nri = f2mul(di, inv);
        ulonglong2 q23 = s_q23[j];
        S0 = f2fma(q23.x, rr, S0);  S1 = f2fma(q23.y, nri, S1);
        S2 = f2fma(q23.y, rr, S2);  S3 = f2fma(q23.x, nri, S3);
        ulonglong2 q45 = s_q45[j];
        S4 = f2fma(q45.x, rr, S4);  S5 = f2fma(q45.y, nri, S5);
        S6 = f2fma(q45.y, rr, S6);  S7 = f2fma(q45.x, nri, S7);
        ulonglong2 q67 = s_q67[j];
        S8 = f2fma(q67.x, rr, S8);   S9 = f2fma(q67.y, nri, S9);
        S10 = f2fma(q67.y, rr, S10); S11 = f2fma(q67.x, nri, S11);
        unsigned long long q8 = s_q8[j];
        S12 = f2fma(q8, rr, S12);    S13 = f2fma(q8, nri, S13);
    }
    float k00r = hsum(S0) + hsum(S1),  k00i = hsum(S2) - hsum(S3);
    float k01r = hsum(S4) + hsum(S5),  k01i = hsum(S6) - hsum(S7);
    float k10r = hsum(S8) + hsum(S9),  k10i = hsum(S10) - hsum(S11);
    float k11r = hsum(S12),            k11i = -hsum(S13);

    float denr = 1.0f + k11r, deni = k11i;
    float invd = 1.0f / (denr * denr + deni * deni);
    float qr = k01r * k10r - k01i * k10i;
    float qi = k01r * k10i + k01i * k10r;
    float fr = (qr * denr + qi * deni) * invd;
    float fi = (qi * denr - qr * deni) * invd;
    float ar_ = k00r - fr, ai_ = k00i - fi;
    g_AT[h * LL + l] = make_float2(csr * ar_ - csi * ai_, csr * ai_ + csi * ar_);
}

__device__ __forceinline__ void transpose_in_body(int j, int t, char* smraw,
                                                  const float* __restrict__ u) {
    float (*tile)[33] = (float (*)[33])smraw;
    int x = j & 15, y = (j >> 4) & 63, b = j >> 10;
    int h0 = x * 32, l0 = y * 32;
    int tx = t & 31, ty = t >> 5;
    const float* up = u + (size_t)b * LL * HN;
#pragma unroll
    for (int k = 0; k < 32; k += 8)
        tile[ty + k][tx] = up[(size_t)(l0 + ty + k) * HN + h0 + tx];
    __syncthreads();
    float* o = g_UT + (size_t)b * HN * LL;
#pragma unroll
    for (int k = 0; k < 32; k += 8)
        o[(size_t)(h0 + ty + k) * LL + l0 + tx] = tile[tx][ty + k];
}

__global__ void __launch_bounds__(NT) k_pre(
        const float* __restrict__ u,
        const float* __restrict__ Lre, const float* __restrict__ Lim,
        const float* __restrict__ P, const float* __restrict__ B,
        const float* __restrict__ C, const float* __restrict__ logstep) {
    __shared__ __align__(16) char smraw[4224];
    int t = threadIdx.x;
    int bid = blockIdx.x;
    if (bid == 0) {
#pragma unroll
        for (int k = t; k < 2048; k += NT) {
            double s, c;
            sincospi(-2.0 * (double)k / 4096.0, &s, &c);
            g_TW[k] = make_float2((float)c, (float)s);
        }
        return;
    }
    int i = bid - 1;                 // [0, 12288)
    int g = i / 3, r = i - 3 * g;    // interleave: 1 cauchy : 2 transpose
    if (r == 0) cauchy_body(g, t, smraw, Lre, Lim, P, B, C, logstep);
    else        transpose_in_body(2 * g + (r - 1), t, smraw, u);
}

// ---------------- K2: kernel spectrum, register radix-16 (round-5 proven) ----------------
#define P1 136
#define P2 258

__global__ void __launch_bounds__(NK) k_kernelfft() {
    __shared__ float2 S0[16 * P1];
    __shared__ float2 S1[16 * P1];
    int h = blockIdx.x, t = threadIdx.x;
    const float2* ath = g_AT + (size_t)h * LL;
    float2* kfh = g_KF + (size_t)h * LF;
    const float s2 = 1.0f / 2048.0f, s4 = 1.0f / 4096.0f;
    float2 v[16];

#pragma unroll
    for (int a = 0; a < 16; a++) {
        int n = a * NK + t;
        float2 x = ath[n];
        float2 m = ath[(2048 - n) & 2047];
        float2 ats = make_float2(0.5f * (x.x + m.x), 0.5f * (x.y - m.y));
        v[a] = ats;
        kfh[2 * n] = make_float2(ats.x * s4, ats.y * s4);
    }
    fft16<+1>(v);
    twchain<1>(v, g_TW[2 * t]);
#pragma unroll
    for (int k1 = 0; k1 < 16; k1++) S0[k1 * P1 + t] = v[k1];
    __syncthreads();

    int k1t = t >> 3, t2 = t & 7;
#pragma unroll
    for (int a2 = 0; a2 < 16; a2++) v[a2] = S0[k1t * P1 + a2 * 8 + t2];
    fft16<+1>(v);
    twchain<1>(v, g_TW[32 * t2]);
#pragma unroll
    for (int k2 = 0; k2 < 16; k2++) S1[t2 * P2 + k2 * 16 + k1t] = v[k2];
    __syncthreads();

#pragma unroll
    for (int e = 0; e < 2; e++) {
        int pr = t + NK * e;
        int k1 = pr & 15, k2 = pr >> 4;
        float2 w[8], X[8];
#pragma unroll
        for (int s = 0; s < 8; s++) w[s] = S1[s * P2 + k2 * 16 + k1];
        bfly8<+1>(w, X);
#pragma unroll
        for (int k3 = 0; k3 < 8; k3++) {
            int n = k1 + 16 * k2 + 256 * k3;
            float kr = X[k3].x * s2;
            float2 tw = g_TW[n];
            S0[n] = make_float2(kr * tw.x, kr * tw.y);
        }
    }
    __syncthreads();

#pragma unroll
    for (int a = 0; a < 16; a++) v[a] = S0[a * NK + t];
    fft16<-1>(v);
    twchain<0>(v, g_TW[2 * t]);
#pragma unroll
    for (int k1 = 0; k1 < 16; k1++) S1[k1 * P1 + t] = v[k1];
    __syncthreads();

#pragma unroll
    for (int a2 = 0; a2 < 16; a2++) v[a2] = S1[k1t * P1 + a2 * 8 + t2];
    fft16<-1>(v);
    twchain<0>(v, g_TW[32 * t2]);
#pragma unroll
    for (int k2 = 0; k2 < 16; k2++) S0[t2 * P2 + k2 * 16 + k1t] = v[k2];
    __syncthreads();

#pragma unroll
    for (int e = 0; e < 2; e++) {
        int pr = t + NK * e;
        int k1 = pr & 15, k2 = pr >> 4;
        float2 w[8], X[8];
#pragma unroll
        for (int s = 0; s < 8; s++) w[s] = S0[s * P2 + k2 * 16 + k1];
        bfly8<-1>(w, X);
#pragma unroll
        for (int k3 = 0; k3 < 8; k3++) {
            int j = k1 + 16 * k2 + 256 * k3;
            kfh[2 * j + 1] = make_float2(X[k3].x * s4, X[k3].y * s4);
        }
    }
}

// ================= conv: register radix-16 + smem-staged KF =================
#define PAD_ROW 257
#define KF_ROW  272

__global__ void __launch_bounds__(NT) k_conv(const float* __restrict__ D) {
    extern __shared__ float2 S[];       // S0[4352] | S1[4112]
    float2* S0 = S;
    float2* S1 = S + 4352;
    int blk = blockIdx.x;
    int h = blk & (HN - 1);
    int bp = blk >> 9;
    int t = threadIdx.x;
    const float* u0 = g_UT + ((size_t)(2 * bp) * HN + h) * LL;
    const float* u1 = g_UT + ((size_t)(2 * bp + 1) * HN + h) * LL;

    float2 v[16];
#pragma unroll
    for (int a = 0; a < 8; a++) v[a] = make_float2(u0[a * 256 + t], u1[a * 256 + t]);
#pragma unroll
    for (int a = 8; a < 16; a++) v[a] = make_float2(0.0f, 0.0f);
    fft16<-1>(v);
    twchain<0>(v, g_TW[t]);
#pragma unroll
    for (int k1 = 0; k1 < 16; k1++) S0[k1 * PAD_ROW + t] = v[k1];
    __syncthreads();
    int c = t & 15, k1 = t >> 4;
#pragma unroll
    for (int b = 0; b < 16; b++) v[b] = S0[k1 * PAD_ROW + b * 16 + c];
    fft16<-1>(v);
    twchain<0>(v, g_TW[c << 4]);
#pragma unroll
    for (int k2 = 0; k2 < 16; k2++) S1[c * PAD_ROW + (k1 << 4) + k2] = v[k2];
    __syncthreads();
#pragma unroll
    for (int cc = 0; cc < 16; cc++) v[cc] = S1[cc * PAD_ROW + t];
    fft16<-1>(v);
    int tinv = ((t & 15) << 4) | (t >> 4);

    // ---- stage KF coalesced into S0, consume at tinv ----
    const float2* kf = g_KF + (size_t)h * LF;
#pragma unroll
    for (int k3 = 0; k3 < 16; k3++)
        S0[k3 * KF_ROW + t + (t >> 4)] = __ldg(&kf[t + (k3 << 8)]);
    __syncthreads();
    int sl = tinv + (tinv >> 4);
#pragma unroll
    for (int k3 = 0; k3 < 16; k3++) v[k3] = cmulf(v[k3], S0[k3 * KF_ROW + sl]);
    __syncthreads();

    fft16<+1>(v);
    twchain<1>(v, g_TW[tinv]);
    {
        int off = (tinv >> 4) + ((tinv & 15) << 4);
#pragma unroll
        for (int j1 = 0; j1 < 16; j1++) S0[j1 * PAD_ROW + off] = v[j1];
    }
    __syncthreads();
    int ct2 = t >> 4, j1b = t & 15;
#pragma unroll
    for (int bt = 0; bt < 16; bt++) v[bt] = S0[j1b * PAD_ROW + bt + (ct2 << 4)];
    fft16<+1>(v);
    twchain<1>(v, g_TW[ct2 << 4]);
#pragma unroll
    for (int j2 = 0; j2 < 16; j2++) S1[ct2 * PAD_ROW + (j2 << 4) + j1b] = v[j2];
    __syncthreads();
#pragma unroll
    for (int ct3 = 0; ct3 < 16; ct3++) v[ct3] = S1[ct3 * PAD_ROW + t];
    fft16<+1>(v);
    float dv = D[h];
    float* y0 = g_YT + ((size_t)(2 * bp) * HN + h) * LL;
    float* y1 = g_YT + ((size_t)(2 * bp + 1) * HN + h) * LL;
#pragma unroll
    for (int j3 = 0; j3 < 8; j3++) {
        int n = t + (j3 << 8);
        y0[n] = fmaf(dv, u0[n], v[j3].x);
        y1[n] = fmaf(dv, u1[n], v[j3].y);
    }
}

// ---------------- K5: transpose y (b,h,l) -> out (b,l,h) ----------------
__global__ void k_transpose_out(float* __restrict__ out) {
    __shared__ float tile[32][33];
    int b = blockIdx.z;
    int l0 = blockIdx.x * 32, h0 = blockIdx.y * 32;
    int tx = threadIdx.x, ty = threadIdx.y;
    const float* yp = g_YT + (size_t)b * HN * LL;
#pragma unroll
    for (int j = 0; j < 32; j += 8)
        tile[ty + j][tx] = yp[(size_t)(h0 + ty + j) * LL + l0 + tx];
    __syncthreads();
    float* op = out + (size_t)b * LL * HN;
#pragma unroll
    for (int j = 0; j < 32; j += 8)
        op[(size_t)(l0 + ty + j) * HN + h0 + tx] = tile[tx][ty + j];
}

// ---------------- launch ----------------
extern "C" void kernel_launch(void* const* d_in, const int* in_sizes, int n_in,
                              void* d_out, int out_size) {
    const float* u   = (const float*)d_in[0];
    const float* Lre = (const float*)d_in[1];
    const float* Lim = (const float*)d_in[2];
    const float* P   = (const float*)d_in[3];
    const float* B   = (const float*)d_in[4];
    const float* C   = (const float*)d_in[5];
    const float* D   = (const float*)d_in[6];
    const float* lst = (const float*)d_in[7];

    const int smem_cv = (4352 + 4112) * sizeof(float2);   // 67712 B
    cudaFuncSetAttribute(k_conv, cudaFuncAttributeMaxDynamicSharedMemorySize, smem_cv);

    k_pre<<<1 + 3 * 4096, NT>>>(u, Lre, Lim, P, B, C, lst);
    k_kernelfft<<<HN, NK>>>();
    k_conv<<<(BT / 2) * HN, NT, smem_cv>>>(D);
    k_transpose_out<<<dim3(LL / 32, HN / 32, BT), dim3(32, 8)>>>((float*)d_out);
}

// round 8
// speedup vs baseline: 1.4531x; 1.0138x over previous
#include <cuda_runtime.h>
#include <math.h>
#include <stdint.h>

#define HN    512
#define NST   64
#define LL    2048
#define LF    4096
#define BT    8
#define NT    256
#define NK    128

// ---------------- scratch ----------------
__device__ float2 g_AT[HN * LL];        // at_roots (h, l)
__device__ float2 g_KF[HN * LF];        // kernel spectrum / 4096
__device__ float  g_UT[BT * HN * LL];   // u transposed (b,h,l)
__device__ float  g_YT[BT * HN * LL];   // y transposed (b,h,l)
__device__ float2 g_TW[2048];           // W_4096^k

// ---------------- helpers ----------------
__device__ __forceinline__ float2 cadd(float2 a, float2 b) { return make_float2(a.x + b.x, a.y + b.y); }
__device__ __forceinline__ float2 csub(float2 a, float2 b) { return make_float2(a.x - b.x, a.y - b.y); }
__device__ __forceinline__ float2 cmulf(float2 a, float2 b) {
    return make_float2(fmaf(a.x, b.x, -(a.y * b.y)), fmaf(a.x, b.y, a.y * b.x));
}

// f32x2 packed math (cauchy)
__device__ __forceinline__ unsigned long long pk2(float a, float b) {
    unsigned long long r; asm("mov.b64 %0, {%1, %2};" : "=l"(r) : "f"(a), "f"(b)); return r;
}
__device__ __forceinline__ void up2(unsigned long long v, float& a, float& b) {
    asm("mov.b64 {%0, %1}, %2;" : "=f"(a), "=f"(b) : "l"(v));
}
__device__ __forceinline__ unsigned long long f2fma(unsigned long long a, unsigned long long b, unsigned long long c) {
    unsigned long long d; asm("fma.rn.f32x2 %0, %1, %2, %3;" : "=l"(d) : "l"(a), "l"(b), "l"(c)); return d;
}
__device__ __forceinline__ unsigned long long f2add(unsigned long long a, unsigned long long b) {
    unsigned long long d; asm("add.rn.f32x2 %0, %1, %2;" : "=l"(d) : "l"(a), "l"(b)); return d;
}
__device__ __forceinline__ unsigned long long f2mul(unsigned long long a, unsigned long long b) {
    unsigned long long d; asm("mul.rn.f32x2 %0, %1, %2;" : "=l"(d) : "l"(a), "l"(b)); return d;
}
__device__ __forceinline__ float rcpa(float x) {
    float r; asm("rcp.approx.f32 %0, %1;" : "=f"(r) : "f"(x)); return r;
}
__device__ __forceinline__ float hsum(unsigned long long v) {
    float a, b; up2(v, a, b); return a + b;
}

// ---------------- register butterflies ----------------
template <int DIR>
__device__ __forceinline__ void bfly8(const float2 v[8], float2 X[8]) {
    float2 s0 = cadd(v[0], v[4]), d0 = csub(v[0], v[4]);
    float2 s1 = cadd(v[2], v[6]), d1 = csub(v[2], v[6]);
    float2 E0 = cadd(s0, s1), E2 = csub(s0, s1);
    float2 id1 = (DIR < 0) ? make_float2(d1.y, -d1.x) : make_float2(-d1.y, d1.x);
    float2 E1 = cadd(d0, id1), E3 = csub(d0, id1);
    float2 t0 = cadd(v[1], v[5]), u0 = csub(v[1], v[5]);
    float2 t1 = cadd(v[3], v[7]), u1 = csub(v[3], v[7]);
    float2 O0 = cadd(t0, t1), O2 = csub(t0, t1);
    float2 iu1 = (DIR < 0) ? make_float2(u1.y, -u1.x) : make_float2(-u1.y, u1.x);
    float2 O1 = cadd(u0, iu1), O3 = csub(u0, iu1);
    const float c = 0.70710678118654752440f;
    float2 w1O1, w2O2, w3O3;
    if (DIR < 0) {
        w1O1 = make_float2(c * (O1.x + O1.y), c * (O1.y - O1.x));
        w2O2 = make_float2(O2.y, -O2.x);
        w3O3 = make_float2(c * (O3.y - O3.x), -c * (O3.x + O3.y));
    } else {
        w1O1 = make_float2(c * (O1.x - O1.y), c * (O1.x + O1.y));
        w2O2 = make_float2(-O2.y, O2.x);
        w3O3 = make_float2(-c * (O3.x + O3.y), c * (O3.x - O3.y));
    }
    X[0] = cadd(E0, O0);   X[4] = csub(E0, O0);
    X[1] = cadd(E1, w1O1); X[5] = csub(E1, w1O1);
    X[2] = cadd(E2, w2O2); X[6] = csub(E2, w2O2);
    X[3] = cadd(E3, w3O3); X[7] = csub(E3, w3O3);
}

template <int DIR>
__device__ __forceinline__ void fft16(float2 v[16]) {
    const float C1 = 0.9238795325112867f;
    const float S1 = 0.3826834323650898f;
    const float R2 = 0.7071067811865476f;
    const float sg = (DIR < 0) ? -1.0f : 1.0f;
    float2 u[16];
#pragma unroll
    for (int j = 0; j < 4; j++) {
        float2 a = v[j], b = v[j + 4], c = v[j + 8], d = v[j + 12];
        float2 A0 = cadd(a, c), A1 = csub(a, c);
        float2 B0 = cadd(b, d), B1 = csub(b, d);
        float2 iB1 = (DIR < 0) ? make_float2(B1.y, -B1.x) : make_float2(-B1.y, B1.x);
        u[j]      = cadd(A0, B0);
        u[4 + j]  = cadd(A1, iB1);
        u[8 + j]  = csub(A0, B0);
        u[12 + j] = csub(A1, iB1);
    }
    u[5]  = cmulf(u[5],  make_float2(C1,  sg * S1));
    u[6]  = cmulf(u[6],  make_float2(R2,  sg * R2));
    u[7]  = cmulf(u[7],  make_float2(S1,  sg * C1));
    u[9]  = cmulf(u[9],  make_float2(R2,  sg * R2));
    u[10] = (DIR < 0) ? make_float2(u[10].y, -u[10].x) : make_float2(-u[10].y, u[10].x);
    u[11] = cmulf(u[11], make_float2(-R2, sg * R2));
    u[13] = cmulf(u[13], make_float2(S1,  sg * C1));
    u[14] = cmulf(u[14], make_float2(-R2, sg * R2));
    u[15] = cmulf(u[15], make_float2(-C1, -sg * S1));
#pragma unroll
    for (int k = 0; k < 4; k++) {
        float2 a = u[k * 4 + 0], b = u[k * 4 + 1], c = u[k * 4 + 2], d = u[k * 4 + 3];
        float2 A0 = cadd(a, c), A1 = csub(a, c);
        float2 B0 = cadd(b, d), B1 = csub(b, d);
        float2 iB1 = (DIR < 0) ? make_float2(B1.y, -B1.x) : make_float2(-B1.y, B1.x);
        v[k]      = cadd(A0, B0);
        v[k + 4]  = cadd(A1, iB1);
        v[k + 8]  = csub(A0, B0);
        v[k + 12] = csub(A1, iB1);
    }
}

template <int CONJ>
__device__ __forceinline__ void twchain(float2 v[16], float2 wt) {
    if (CONJ) wt.y = -wt.y;
    float2 w = wt;
#pragma unroll
    for (int k = 1; k < 16; k++) {
        v[k] = cmulf(v[k], w);
        if (k < 15) w = cmulf(w, wt);
    }
}

// ================= K_pre: fused twiddle + transpose_in + cauchy (round-6 proven) =================

__device__ __forceinline__ void cauchy_body(
        int i, int t, char* smraw,
        const float* __restrict__ Lre, const float* __restrict__ Lim,
        const float* __restrict__ P, const float* __restrict__ B,
        const float* __restrict__ C, const float* __restrict__ logstep) {
    ulonglong2* s_q01 = (ulonglong2*)smraw;
    ulonglong2* s_q23 = s_q01 + 32;
    ulonglong2* s_q45 = s_q23 + 32;
    ulonglong2* s_q67 = s_q45 + 32;
    unsigned long long* s_q8 = (unsigned long long*)(s_q67 + 32);
    int h = i >> 3;
    int bx = i & 7;
    if (t < 32) {
        float lr[2], li[2], w00r[2], w00i[2], w01r[2], w01i[2], w10r[2], w10i[2], w11r[2];
#pragma unroll
        for (int k = 0; k < 2; k++) {
            int idx = h * NST + 2 * t + k;
            lr[k] = fminf(Lre[idx], -1e-4f);
            li[k] = Lim[idx];
            float pr = P[idx * 2], pi = P[idx * 2 + 1];
            float br = B[idx * 2], bi = B[idx * 2 + 1];
            float cr = C[idx * 2], ci = C[idx * 2 + 1];
            w00r[k] = cr * br + ci * bi;  w00i[k] = cr * bi - ci * br;
            w01r[k] = cr * pr + ci * pi;  w01i[k] = cr * pi - ci * pr;
            w10r[k] = pr * br + pi * bi;  w10i[k] = pr * bi - pi * br;
            w11r[k] = pr * pr + pi * pi;
        }
        s_q01[t] = make_ulonglong2(pk2(-lr[0], -lr[1]), pk2(-li[0], -li[1]));
        s_q23[t] = make_ulonglong2(pk2(w00r[0], w00r[1]), pk2(w00i[0], w00i[1]));
        s_q45[t] = make_ulonglong2(pk2(w01r[0], w01r[1]), pk2(w01i[0], w01i[1]));
        s_q67[t] = make_ulonglong2(pk2(w10r[0], w10r[1]), pk2(w10i[0], w10i[1]));
        s_q8[t]  = pk2(w11r[0], w11r[1]);
    }
    __syncthreads();

    int l = bx * NT + t;
    float ts = 2.0f * expf(-logstep[h]);
    float theta = (float)l * (-2.0f * 3.14159265358979323846f / (float)LL);
    float sn, cs;
    sincosf(theta, &sn, &cs);
    float bpr = 1.0f + cs, bpi = sn;
    float amr = 1.0f - cs, ami = -sn;
    float invb = 1.0f / (bpr * bpr + bpi * bpi);
    float gr = ts * (amr * bpr + ami * bpi) * invb;
    float gi = ts * (ami * bpr - amr * bpi) * invb;
    float csr = 2.0f * bpr * invb;
    float csi = -2.0f * bpi * invb;

    unsigned long long gr2 = pk2(gr, gr), gi2 = pk2(gi, gi);
    unsigned long long S0 = 0, S1 = 0, S2 = 0, S3 = 0, S4 = 0, S5 = 0, S6 = 0;
    unsigned long long S7 = 0, S8 = 0, S9 = 0, S10 = 0, S11 = 0, S12 = 0, S13 = 0;
#pragma unroll 8
    for (int j = 0; j < 32; j++) {
        ulonglong2 q01 = s_q01[j];
        unsigned long long dr = f2add(gr2, q01.x);
        unsigned long long di = f2add(gi2, q01.y);
        unsigned long long mag = f2fma(dr, dr, f2mul(di, di));
        float m0, m1; up2(mag, m0, m1);
        unsigned long long inv = pk2(rcpa(m0), rcpa(m1));
        unsigned long long rr  = f2mul(dr, inv);
        unsigned long long nri = f2mul(di, inv);
        ulonglong2 q23 = s_q23[j];
        S0 = f2fma(q23.x, rr, S0);  S1 = f2fma(q23.y, nri, S1);
        S2 = f2fma(q23.y, rr, S2);  S3 = f2fma(q23.x, nri, S3);
        ulonglong2 q45 = s_q45[j];
        S4 = f2fma(q45.x, rr, S4);  S5 = f2fma(q45.y, nri, S5);
        S6 = f2fma(q45.y, rr, S6);  S7 = f2fma(q45.x, nri, S7);
        ulonglong2 q67 = s_q67[j];
        S8 = f2fma(q67.x, rr, S8);   S9 = f2fma(q67.y, nri, S9);
        S10 = f2fma(q67.y, rr, S10); S11 = f2fma(q67.x, nri, S11);
        unsigned long long q8 = s_q8[j];
        S12 = f2fma(q8, rr, S12);    S13 = f2fma(q8, nri, S13);
    }
    float k00r = hsum(S0) + hsum(S1),  k00i = hsum(S2) - hsum(S3);
    float k01r = hsum(S4) + hsum(S5),  k01i = hsum(S6) - hsum(S7);
    float k10r = hsum(S8) + hsum(S9),  k10i = hsum(S10) - hsum(S11);
    float k11r = hsum(S12),            k11i = -hsum(S13);

    float denr = 1.0f + k11r, deni = k11i;
    float invd = 1.0f / (denr * denr + deni * deni);
    float qr = k01r * k10r - k01i * k10i;
    float qi = k01r * k10i + k01i * k10r;
    float fr = (qr * denr + qi * deni) * invd;
    float fi = (qi * denr - qr * deni) * invd;
    float ar_ = k00r - fr, ai_ = k00i - fi;
    g_AT[h * LL + l] = make_float2(csr * ar_ - csi * ai_, csr * ai_ + csi * ar_);
}

__device__ __forceinline__ void transpose_in_body(int j, int t, char* smraw,
                                                  const float* __restrict__ u) {
    float (*tile)[33] = (float (*)[33])smraw;
    int x = j & 15, y = (j >> 4) & 63, b = j >> 10;
    int h0 = x * 32, l0 = y * 32;
    int tx = t & 31, ty = t >> 5;
    const float* up = u + (size_t)b * LL * HN;
#pragma unroll
    for (int k = 0; k < 32; k += 8)
        tile[ty + k][tx] = up[(size_t)(l0 + ty + k) * HN + h0 + tx];
    __syncthreads();
    float* o = g_UT + (size_t)b * HN * LL;
#pragma unroll
    for (int k = 0; k < 32; k += 8)
        o[(size_t)(h0 + ty + k) * LL + l0 + tx] = tile[tx][ty + k];
}

__global__ void __launch_bounds__(NT) k_pre(
        const float* __restrict__ u,
        const float* __restrict__ Lre, const float* __restrict__ Lim,
        const float* __restrict__ P, const float* __restrict__ B,
        const float* __restrict__ C, const float* __restrict__ logstep) {
    __shared__ __align__(16) char smraw[4224];
    int t = threadIdx.x;
    int bid = blockIdx.x;
    if (bid == 0) {
#pragma unroll
        for (int k = t; k < 2048; k += NT) {
            double s, c;
            sincospi(-2.0 * (double)k / 4096.0, &s, &c);
            g_TW[k] = make_float2((float)c, (float)s);
        }
        return;
    }
    int i = bid - 1;
    int g = i / 3, r = i - 3 * g;
    if (r == 0) cauchy_body(g, t, smraw, Lre, Lim, P, B, C, logstep);
    else        transpose_in_body(2 * g + (r - 1), t, smraw, u);
}

// ---------------- K2: kernel spectrum, register radix-16 (round-5 proven) ----------------
#define P1 136
#define P2 258

__global__ void __launch_bounds__(NK) k_kernelfft() {
    __shared__ float2 S0[16 * P1];
    __shared__ float2 S1[16 * P1];
    int h = blockIdx.x, t = threadIdx.x;
    const float2* ath = g_AT + (size_t)h * LL;
    float2* kfh = g_KF + (size_t)h * LF;
    const float s2 = 1.0f / 2048.0f, s4 = 1.0f / 4096.0f;
    float2 v[16];

#pragma unroll
    for (int a = 0; a < 16; a++) {
        int n = a * NK + t;
        float2 x = ath[n];
        float2 m = ath[(2048 - n) & 2047];
        float2 ats = make_float2(0.5f * (x.x + m.x), 0.5f * (x.y - m.y));
        v[a] = ats;
        kfh[2 * n] = make_float2(ats.x * s4, ats.y * s4);
    }
    fft16<+1>(v);
    twchain<1>(v, g_TW[2 * t]);
#pragma unroll
    for (int k1 = 0; k1 < 16; k1++) S0[k1 * P1 + t] = v[k1];
    __syncthreads();

    int k1t = t >> 3, t2 = t & 7;
#pragma unroll
    for (int a2 = 0; a2 < 16; a2++) v[a2] = S0[k1t * P1 + a2 * 8 + t2];
    fft16<+1>(v);
    twchain<1>(v, g_TW[32 * t2]);
#pragma unroll
    for (int k2 = 0; k2 < 16; k2++) S1[t2 * P2 + k2 * 16 + k1t] = v[k2];
    __syncthreads();

#pragma unroll
    for (int e = 0; e < 2; e++) {
        int pr = t + NK * e;
        int k1 = pr & 15, k2 = pr >> 4;
        float2 w[8], X[8];
#pragma unroll
        for (int s = 0; s < 8; s++) w[s] = S1[s * P2 + k2 * 16 + k1];
        bfly8<+1>(w, X);
#pragma unroll
        for (int k3 = 0; k3 < 8; k3++) {
            int n = k1 + 16 * k2 + 256 * k3;
            float kr = X[k3].x * s2;
            float2 tw = g_TW[n];
            S0[n] = make_float2(kr * tw.x, kr * tw.y);
        }
    }
    __syncthreads();

#pragma unroll
    for (int a = 0; a < 16; a++) v[a] = S0[a * NK + t];
    fft16<-1>(v);
    twchain<0>(v, g_TW[2 * t]);
#pragma unroll
    for (int k1 = 0; k1 < 16; k1++) S1[k1 * P1 + t] = v[k1];
    __syncthreads();

#pragma unroll
    for (int a2 = 0; a2 < 16; a2++) v[a2] = S1[k1t * P1 + a2 * 8 + t2];
    fft16<-1>(v);
    twchain<0>(v, g_TW[32 * t2]);
#pragma unroll
    for (int k2 = 0; k2 < 16; k2++) S0[t2 * P2 + k2 * 16 + k1t] = v[k2];
    __syncthreads();

#pragma unroll
    for (int e = 0; e < 2; e++) {
        int pr = t + NK * e;
        int k1 = pr & 15, k2 = pr >> 4;
        float2 w[8], X[8];
#pragma unroll
        for (int s = 0; s < 8; s++) w[s] = S0[s * P2 + k2 * 16 + k1];
        bfly8<-1>(w, X);
#pragma unroll
        for (int k3 = 0; k3 < 8; k3++) {
            int j = k1 + 16 * k2 + 256 * k3;
            kfh[2 * j + 1] = make_float2(X[k3].x * s4, X[k3].y * s4);
        }
    }
}

// ================= conv: register radix-16, natural-order via 17-stride exch2 =================
// Exchange-2 row pitch must hold slot 17*k1 + k2 (max 270) -> P2C = 273 (273 % 16 == 1,
// keeps bank residue = c + k1 + k2, conflict-free per half-warp).
#define PAD_ROW 257
#define P2C     273

__global__ void __launch_bounds__(NT) k_conv(const float* __restrict__ D) {
    extern __shared__ float2 S[];       // S0[4112] | S1[4368]
    float2* S0 = S;
    float2* S1 = S + 4112;
    int blk = blockIdx.x;
    int h = blk & (HN - 1);
    int bp = blk >> 9;
    int t = threadIdx.x;
    const float* u0 = g_UT + ((size_t)(2 * bp) * HN + h) * LL;
    const float* u1 = g_UT + ((size_t)(2 * bp + 1) * HN + h) * LL;

    int c = t & 15, k1r = t >> 4;
    int sj = 17 * c + k1r;             // slot of G2(k1=t&15, k2=t>>4)
    float2 wA = g_TW[t];               // W4096^t
    float2 wB = g_TW[c << 4];          // W256^c

    float2 v[16];
    // ---- forward ----
#pragma unroll
    for (int a = 0; a < 8; a++) v[a] = make_float2(u0[a * 256 + t], u1[a * 256 + t]);
#pragma unroll
    for (int a = 8; a < 16; a++) v[a] = make_float2(0.0f, 0.0f);
    fft16<-1>(v);
    twchain<0>(v, wA);
#pragma unroll
    for (int k1 = 0; k1 < 16; k1++) S0[k1 * PAD_ROW + t] = v[k1];
    __syncthreads();
#pragma unroll
    for (int b = 0; b < 16; b++) v[b] = S0[k1r * PAD_ROW + b * 16 + c];
    fft16<-1>(v);
    twchain<0>(v, wB);
#pragma unroll
    for (int k2 = 0; k2 < 16; k2++) S1[c * P2C + 17 * k1r + k2] = v[k2];
    __syncthreads();
#pragma unroll
    for (int cc = 0; cc < 16; cc++) v[cc] = S1[cc * P2C + sj];
    fft16<-1>(v);
    // thread t holds X[t + 256*k3] — natural order

    // ---- pointwise * KF/4096 (coalesced, no staging) ----
    const float2* kf = g_KF + (size_t)h * LF;
#pragma unroll
    for (int k3 = 0; k3 < 16; k3++) v[k3] = cmulf(v[k3], __ldg(&kf[(k3 << 8) + t]));

    // ---- inverse: exact mirror of forward, conj twiddles ----
    fft16<+1>(v);
    twchain<1>(v, wA);
#pragma unroll
    for (int j1 = 0; j1 < 16; j1++) S0[j1 * PAD_ROW + t] = v[j1];
    __syncthreads();
#pragma unroll
    for (int b = 0; b < 16; b++) v[b] = S0[k1r * PAD_ROW + b * 16 + c];
    fft16<+1>(v);
    twchain<1>(v, wB);
#pragma unroll
    for (int j2 = 0; j2 < 16; j2++) S1[c * P2C + 17 * k1r + j2] = v[j2];
    __syncthreads();
#pragma unroll
    for (int cc = 0; cc < 16; cc++) v[cc] = S1[cc * P2C + sj];
    fft16<+1>(v);
    // thread t holds y[t + 256*j3]; keep j3<8, add D skip
    float dv = D[h];
    float* y0 = g_YT + ((size_t)(2 * bp) * HN + h) * LL;
    float* y1 = g_YT + ((size_t)(2 * bp + 1) * HN + h) * LL;
#pragma unroll
    for (int j3 = 0; j3 < 8; j3++) {
        int n = t + (j3 << 8);
        y0[n] = fmaf(dv, u0[n], v[j3].x);
        y1[n] = fmaf(dv, u1[n], v[j3].y);
    }
}

// ---------------- K5: transpose y (b,h,l) -> out (b,l,h) ----------------
__global__ void k_transpose_out(float* __restrict__ out) {
    __shared__ float tile[32][33];
    int b = blockIdx.z;
    int l0 = blockIdx.x * 32, h0 = blockIdx.y * 32;
    int tx = threadIdx.x, ty = threadIdx.y;
    const float* yp = g_YT + (size_t)b * HN * LL;
#pragma unroll
    for (int j = 0; j < 32; j += 8)
        tile[ty + j][tx] = yp[(size_t)(h0 + ty + j) * LL + l0 + tx];
    __syncthreads();
    float* op = out + (size_t)b * LL * HN;
#pragma unroll
    for (int j = 0; j < 32; j += 8)
        op[(size_t)(l0 + ty + j) * HN + h0 + tx] = tile[tx][ty + j];
}

// ---------------- launch ----------------
extern "C" void kernel_launch(void* const* d_in, const int* in_sizes, int n_in,
                              void* d_out, int out_size) {
    const float* u   = (const float*)d_in[0];
    const float* Lre = (const float*)d_in[1];
    const float* Lim = (const float*)d_in[2];
    const float* P   = (const float*)d_in[3];
    const float* B   = (const float*)d_in[4];
    const float* C   = (const float*)d_in[5];
    const float* D   = (const float*)d_in[6];
    const float* lst = (const float*)d_in[7];

    const int smem_cv = (4112 + 4368) * sizeof(float2);   // 67840 B
    cudaFuncSetAttribute(k_conv, cudaFuncAttributeMaxDynamicSharedMemorySize, smem_cv);

    k_pre<<<1 + 3 * 4096, NT>>>(u, Lre, Lim, P, B, C, lst);
    k_kernelfft<<<HN, NK>>>();
    k_conv<<<(BT / 2) * HN, NT, smem_cv>>>(D);
    k_transpose_out<<<dim3(LL / 32, HN / 32, BT), dim3(32, 8)>>>((float*)d_out);
}